// round 1
// baseline (speedup 1.0000x reference)
#include <cuda_runtime.h>
#include <math.h>

#define NTOT   65536
#define NGRAPH 128
#define NPG    512
#define KPOOL  256
#define EDG    524288
#define IND    128
#define H1     256
#define H2     128

// ---------------- scratch (device globals; no allocation) ----------------
__device__ float    d_deg[NTOT];
__device__ float    d_dinv[NTOT];
__device__ float    d_tx1[NTOT * IND];
__device__ float    d_h  [NTOT * H1];
__device__ float    d_z  [NTOT * H2];
__device__ float    d_as [NTOT];
__device__ float    d_ad [NTOT];
__device__ unsigned d_menc[NTOT];
__device__ float    d_mf [NTOT];
__device__ float    d_ssum[NTOT];
__device__ float    d_earr[EDG];
__device__ float    d_g  [NTOT * H2];
__device__ float    d_score[NTOT];
__device__ float    d_gm [NGRAPH * H2];
__device__ float    d_invpnorm;

// ---------------- helpers ----------------
__device__ __forceinline__ float lrelu(float x) { return x > 0.f ? x : 0.2f * x; }

__device__ __forceinline__ unsigned fenc(float f) {
    unsigned u = __float_as_uint(f);
    return (u & 0x80000000u) ? ~u : (u | 0x80000000u);
}
__device__ __forceinline__ float fdec(unsigned u) {
    return (u & 0x80000000u) ? __uint_as_float(u & 0x7fffffffu) : __uint_as_float(~u);
}

// ---------------- kernels ----------------
// zero tx1 (as float4) and deg
__global__ void k_zero() {
    int idx = blockIdx.x * blockDim.x + threadIdx.x;         // over NTOT*32 float4
    if (idx < NTOT * (IND / 4))
        ((float4*)d_tx1)[idx] = make_float4(0.f, 0.f, 0.f, 0.f);
    if (idx < NTOT) d_deg[idx] = 0.f;
}

__global__ void k_deg(const int* __restrict__ row, int E) {
    int e = blockIdx.x * blockDim.x + threadIdx.x;
    if (e < E) atomicAdd(&d_deg[row[e]], 1.0f);
}

__global__ void k_dinv(int n) {
    int i = blockIdx.x * blockDim.x + threadIdx.x;
    if (i < n) {
        float dg = d_deg[i];
        d_dinv[i] = dg > 0.f ? rsqrtf(fmaxf(dg, 1.0f)) : 0.f;
    }
}

// ChebConv scatter: tx1[col] += (-dinv[row]*dinv[col]) * x[row] ; warp per edge
__global__ void k_cheb_scatter(const int* __restrict__ row, const int* __restrict__ col,
                               const float* __restrict__ x, int E) {
    int wid  = (blockIdx.x * blockDim.x + threadIdx.x) >> 5;
    int lane = threadIdx.x & 31;
    if (wid >= E) return;
    int r = row[wid], c = col[wid];
    float w = -d_dinv[r] * d_dinv[c];
    float4 xv = *(const float4*)(x + r * IND + lane * 4);
    float* dst = d_tx1 + c * IND + lane * 4;
    atomicAdd(dst + 0, w * xv.x);
    atomicAdd(dst + 1, w * xv.y);
    atomicAdd(dst + 2, w * xv.z);
    atomicAdd(dst + 3, w * xv.w);
}

// h = relu(x@W0 + tx1@W1 + bias) : M=NTOT, N=256, virtual K=256 (concat)
__global__ __launch_bounds__(256) void k_gemm_h(const float* __restrict__ x,
                                                const float* __restrict__ w0,
                                                const float* __restrict__ w1,
                                                const float* __restrict__ bias) {
    __shared__ float As[16][65];
    __shared__ float Bs[16][64];
    int tid = threadIdx.x;
    int tx = tid & 15, ty = tid >> 4;
    int m0 = blockIdx.y * 64, n0 = blockIdx.x * 64;
    float acc[4][4] = {};
    for (int k0 = 0; k0 < 256; k0 += 16) {
        {   // A tile: 64 rows x 16 k, one float4 per thread
            int r = tid >> 2, kq = (tid & 3) * 4;
            int kk = k0 + kq;
            const float* src = (kk < 128) ? (x + (m0 + r) * IND + kk)
                                          : (d_tx1 + (m0 + r) * IND + (kk - 128));
            float4 v = *(const float4*)src;
            As[kq + 0][r] = v.x; As[kq + 1][r] = v.y;
            As[kq + 2][r] = v.z; As[kq + 3][r] = v.w;
        }
        {   // B tile: 16 k x 64 n
            int kr = tid >> 4, nq = (tid & 15) * 4;
            int kk = k0 + kr;
            const float* src = (kk < 128) ? (w0 + kk * H1 + n0 + nq)
                                          : (w1 + (kk - 128) * H1 + n0 + nq);
            *(float4*)&Bs[kr][nq] = *(const float4*)src;
        }
        __syncthreads();
        #pragma unroll
        for (int kk = 0; kk < 16; kk++) {
            float a[4];
            #pragma unroll
            for (int i = 0; i < 4; i++) a[i] = As[kk][ty * 4 + i];
            float4 b4 = *(float4*)&Bs[kk][tx * 4];
            float b[4] = {b4.x, b4.y, b4.z, b4.w};
            #pragma unroll
            for (int i = 0; i < 4; i++)
                #pragma unroll
                for (int j = 0; j < 4; j++) acc[i][j] += a[i] * b[j];
        }
        __syncthreads();
    }
    #pragma unroll
    for (int i = 0; i < 4; i++) {
        int m = m0 + ty * 4 + i;
        #pragma unroll
        for (int j = 0; j < 4; j++) {
            int nn = n0 + tx * 4 + j;
            d_h[m * H1 + nn] = fmaxf(acc[i][j] + bias[nn], 0.f);
        }
    }
}

// z = h @ gat_w : M=NTOT, N=128, K=256
__global__ __launch_bounds__(256) void k_gemm_z(const float* __restrict__ w) {
    __shared__ float As[16][65];
    __shared__ float Bs[16][64];
    int tid = threadIdx.x;
    int tx = tid & 15, ty = tid >> 4;
    int m0 = blockIdx.y * 64, n0 = blockIdx.x * 64;
    float acc[4][4] = {};
    for (int k0 = 0; k0 < 256; k0 += 16) {
        {
            int r = tid >> 2, kq = (tid & 3) * 4;
            float4 v = *(const float4*)(d_h + (m0 + r) * H1 + k0 + kq);
            As[kq + 0][r] = v.x; As[kq + 1][r] = v.y;
            As[kq + 2][r] = v.z; As[kq + 3][r] = v.w;
        }
        {
            int kr = tid >> 4, nq = (tid & 15) * 4;
            *(float4*)&Bs[kr][nq] = *(const float4*)(w + (k0 + kr) * H2 + n0 + nq);
        }
        __syncthreads();
        #pragma unroll
        for (int kk = 0; kk < 16; kk++) {
            float a[4];
            #pragma unroll
            for (int i = 0; i < 4; i++) a[i] = As[kk][ty * 4 + i];
            float4 b4 = *(float4*)&Bs[kk][tx * 4];
            float b[4] = {b4.x, b4.y, b4.z, b4.w};
            #pragma unroll
            for (int i = 0; i < 4; i++)
                #pragma unroll
                for (int j = 0; j < 4; j++) acc[i][j] += a[i] * b[j];
        }
        __syncthreads();
    }
    #pragma unroll
    for (int i = 0; i < 4; i++) {
        int m = m0 + ty * 4 + i;
        #pragma unroll
        for (int j = 0; j < 4; j++)
            d_z[m * H2 + n0 + tx * 4 + j] = acc[i][j];
    }
}

// per-node attention coefs a_s, a_d + init segment-max with self-loop value; warp/node
__global__ void k_attn_coef(const float* __restrict__ asrc, const float* __restrict__ adst, int n) {
    int i    = (blockIdx.x * blockDim.x + threadIdx.x) >> 5;
    int lane = threadIdx.x & 31;
    if (i >= n) return;
    float4 zv = *(const float4*)(d_z + i * H2 + lane * 4);
    float4 av = *(const float4*)(asrc + lane * 4);
    float4 bv = *(const float4*)(adst + lane * 4);
    float s = zv.x * av.x + zv.y * av.y + zv.z * av.z + zv.w * av.w;
    float d = zv.x * bv.x + zv.y * bv.y + zv.z * bv.z + zv.w * bv.w;
    #pragma unroll
    for (int o = 16; o > 0; o >>= 1) {
        s += __shfl_down_sync(0xffffffffu, s, o);
        d += __shfl_down_sync(0xffffffffu, d, o);
    }
    if (lane == 0) {
        d_as[i] = s; d_ad[i] = d;
        d_menc[i] = fenc(lrelu(s + d));   // self-loop term
    }
}

__global__ void k_edge_max(const int* __restrict__ row, const int* __restrict__ col, int E) {
    int e = blockIdx.x * blockDim.x + threadIdx.x;
    if (e >= E) return;
    int r = row[e], c = col[e];
    float ev = lrelu(d_as[r] + d_ad[c]);
    d_earr[e] = ev;
    atomicMax(&d_menc[c], fenc(ev));
}

__global__ void k_ssum_init(int n) {
    int i = blockIdx.x * blockDim.x + threadIdx.x;
    if (i >= n) return;
    float m = fdec(d_menc[i]);
    d_mf[i] = m;
    d_ssum[i] = expf(lrelu(d_as[i] + d_ad[i]) - m);   // self-loop term
}

__global__ void k_edge_ssum(const int* __restrict__ col, int E) {
    int e = blockIdx.x * blockDim.x + threadIdx.x;
    if (e >= E) return;
    int c = col[e];
    atomicAdd(&d_ssum[c], expf(d_earr[e] - d_mf[c]));
}

// g init with self-loop contribution
__global__ void k_g_init(int n) {
    int idx = blockIdx.x * blockDim.x + threadIdx.x;
    if (idx >= n * H2) return;
    int i = idx >> 7;
    float coef = expf(lrelu(d_as[i] + d_ad[i]) - d_mf[i]) / d_ssum[i];
    d_g[idx] = coef * d_z[idx];
}

// g[col] += alpha * z[row] ; warp per edge
__global__ void k_g_scatter(const int* __restrict__ row, const int* __restrict__ col, int E) {
    int wid  = (blockIdx.x * blockDim.x + threadIdx.x) >> 5;
    int lane = threadIdx.x & 31;
    if (wid >= E) return;
    int r = row[wid], c = col[wid];
    float w = expf(d_earr[wid] - d_mf[c]) / d_ssum[c];
    float4 zv = *(const float4*)(d_z + r * H2 + lane * 4);
    float* dst = d_g + c * H2 + lane * 4;
    atomicAdd(dst + 0, w * zv.x);
    atomicAdd(dst + 1, w * zv.y);
    atomicAdd(dst + 2, w * zv.z);
    atomicAdd(dst + 3, w * zv.w);
}

__global__ void k_pnorm(const float* __restrict__ p) {
    __shared__ float sh[128];
    int t = threadIdx.x;
    float v = p[t];
    sh[t] = v * v;
    __syncthreads();
    for (int o = 64; o > 0; o >>= 1) {
        if (t < o) sh[t] += sh[t + o];
        __syncthreads();
    }
    if (t == 0) d_invpnorm = 1.0f / sqrtf(sh[0]);
}

// g = relu(g + gat_b), score = tanh(g.p / ||p||) ; warp per node
__global__ void k_relu_score(const float* __restrict__ gb, const float* __restrict__ p, int n) {
    int i    = (blockIdx.x * blockDim.x + threadIdx.x) >> 5;
    int lane = threadIdx.x & 31;
    if (i >= n) return;
    float4 gv = *(float4*)(d_g + i * H2 + lane * 4);
    float4 bv = *(const float4*)(gb + lane * 4);
    gv.x = fmaxf(gv.x + bv.x, 0.f); gv.y = fmaxf(gv.y + bv.y, 0.f);
    gv.z = fmaxf(gv.z + bv.z, 0.f); gv.w = fmaxf(gv.w + bv.w, 0.f);
    *(float4*)(d_g + i * H2 + lane * 4) = gv;
    float4 pv = *(const float4*)(p + lane * 4);
    float s = gv.x * pv.x + gv.y * pv.y + gv.z * pv.z + gv.w * pv.w;
    #pragma unroll
    for (int o = 16; o > 0; o >>= 1) s += __shfl_down_sync(0xffffffffu, s, o);
    if (lane == 0) d_score[i] = tanhf(s * d_invpnorm);
}

// per-graph top-256 of 512 via bitonic sort + gated mean pool -> gm[b][:]
__global__ __launch_bounds__(256) void k_topk_pool() {
    __shared__ float sv[NPG];
    __shared__ int   si[NPG];
    __shared__ float part[256];
    int b = blockIdx.x, t = threadIdx.x;
    int base = b * NPG;
    sv[t]        = d_score[base + t];        si[t]        = t;
    sv[t + 256]  = d_score[base + t + 256];  si[t + 256]  = t + 256;
    __syncthreads();
    for (int k = 2; k <= NPG; k <<= 1) {
        for (int j = k >> 1; j > 0; j >>= 1) {
            #pragma unroll
            for (int s = 0; s < 2; s++) {
                int i = t + s * 256;
                int ixj = i ^ j;
                if (ixj > i) {
                    bool up = ((i & k) == 0);            // descending overall
                    float vi = sv[i], vj = sv[ixj];
                    bool sw = up ? (vi < vj) : (vi > vj);
                    if (sw) {
                        sv[i] = vj; sv[ixj] = vi;
                        int ti = si[i]; si[i] = si[ixj]; si[ixj] = ti;
                    }
                }
            }
            __syncthreads();
        }
    }
    // gated mean over the top KPOOL rows
    int d = t & 127, half = t >> 7;         // half 0: j 0..127, half 1: j 128..255
    float acc = 0.f;
    for (int j = half * 128; j < half * 128 + 128; j++) {
        acc += d_g[(base + si[j]) * H2 + d] * sv[j];
    }
    part[t] = acc;
    __syncthreads();
    if (t < 128) d_gm[b * H2 + t] = (part[t] + part[t + 128]) * (1.0f / (float)KPOOL);
}

// out[b] = relu(gm@lin1 + b1) @ lin2 + b2
__global__ __launch_bounds__(256) void k_mlp(const float* __restrict__ w1,
                                             const float* __restrict__ b1,
                                             const float* __restrict__ w2,
                                             const float* __restrict__ b2,
                                             float* __restrict__ out) {
    __shared__ float sgm[H2];
    __shared__ float red[256];
    int b = blockIdx.x, t = threadIdx.x;
    if (t < H2) sgm[t] = d_gm[b * H2 + t];
    __syncthreads();
    float acc = b1[t];
    #pragma unroll 8
    for (int k = 0; k < H2; k++) acc += sgm[k] * w1[k * H1 + t];
    red[t] = fmaxf(acc, 0.f) * w2[t];
    __syncthreads();
    for (int o = 128; o > 0; o >>= 1) {
        if (t < o) red[t] += red[t + o];
        __syncthreads();
    }
    if (t == 0) out[b] = red[0] + b2[0];
}

// ---------------- launch ----------------
extern "C" void kernel_launch(void* const* d_in, const int* in_sizes, int n_in,
                              void* d_out, int out_size) {
    const float* x     = (const float*)d_in[0];
    const int*   ei    = (const int*)  d_in[1];
    const float* cw0   = (const float*)d_in[3];
    const float* cw1   = (const float*)d_in[4];
    const float* cb    = (const float*)d_in[5];
    const float* gw    = (const float*)d_in[6];
    const float* gas   = (const float*)d_in[7];
    const float* gad   = (const float*)d_in[8];
    const float* gb    = (const float*)d_in[9];
    const float* pp    = (const float*)d_in[10];
    const float* l1w   = (const float*)d_in[11];
    const float* l1b   = (const float*)d_in[12];
    const float* l2w   = (const float*)d_in[13];
    const float* l2b   = (const float*)d_in[14];
    float* out = (float*)d_out;

    int n = in_sizes[0] / IND;          // 65536
    int E = in_sizes[1] / 2;            // 524288
    const int* row = ei;
    const int* col = ei + E;

    k_zero<<<(NTOT * (IND / 4) + 255) / 256, 256>>>();
    k_deg<<<(E + 255) / 256, 256>>>(row, E);
    k_dinv<<<(n + 255) / 256, 256>>>(n);
    k_cheb_scatter<<<(E * 32 + 255) / 256, 256>>>(row, col, x, E);

    dim3 gh(H1 / 64, NTOT / 64);
    k_gemm_h<<<gh, 256>>>(x, cw0, cw1, cb);
    dim3 gz(H2 / 64, NTOT / 64);
    k_gemm_z<<<gz, 256>>>(gw);

    k_attn_coef<<<(n * 32 + 255) / 256, 256>>>(gas, gad, n);
    k_edge_max<<<(E + 255) / 256, 256>>>(row, col, E);
    k_ssum_init<<<(n + 255) / 256, 256>>>(n);
    k_edge_ssum<<<(E + 255) / 256, 256>>>(col, E);
    k_g_init<<<(n * H2 + 255) / 256, 256>>>(n);
    k_g_scatter<<<(E * 32 + 255) / 256, 256>>>(row, col, E);

    k_pnorm<<<1, 128>>>(pp);
    k_relu_score<<<(n * 32 + 255) / 256, 256>>>(gb, pp, n);
    k_topk_pool<<<NGRAPH, 256>>>();
    k_mlp<<<NGRAPH, 256>>>(l1w, l1b, l2w, l2b, out);
}

// round 4
// speedup vs baseline: 1.5746x; 1.5746x over previous
#include <cuda_runtime.h>
#include <math.h>

#define NTOT   65536
#define NGRAPH 128
#define NPG    512
#define KPOOL  256
#define EDG    524288
#define IND    128
#define H1     256
#define H2     128

// ---------------- scratch (device globals; no allocation) ----------------
__device__ int      d_degi[NTOT];      // out-degree (row)
__device__ float    d_dinv[NTOT];
__device__ int      d_cntin[NTOT];     // in-degree (col)
__device__ int      d_cstart[NTOT];    // CSR row starts (by col)
__device__ int      d_cfill[NTOT];
__device__ int      d_bsum[64];
__device__ int      d_boff[64];
__device__ int      d_csr[EDG];        // edge ids -> (after sort) source node ids, by dst
__device__ float    d_tx1[NTOT * IND];
__device__ float    d_h  [NTOT * H1];
__device__ float    d_z  [NTOT * H2];
__device__ float    d_as [NTOT];
__device__ float    d_ad [NTOT];
__device__ float    d_g  [NTOT * H2];
__device__ float    d_score[NTOT];
__device__ float    d_gm [NGRAPH * H2];
__device__ float    d_invpnorm;

// ---------------- helpers ----------------
__device__ __forceinline__ float lrelu(float x) { return x > 0.f ? x : 0.2f * x; }

// ---------------- CSR build ----------------
__global__ void k_zero() {
    int i = blockIdx.x * blockDim.x + threadIdx.x;
    if (i < NTOT) { d_degi[i] = 0; d_cntin[i] = 0; d_cfill[i] = 0; }
}

__global__ void k_count(const int* __restrict__ row, const int* __restrict__ col, int E) {
    int e = blockIdx.x * blockDim.x + threadIdx.x;
    if (e < E) {
        atomicAdd(&d_degi[row[e]], 1);
        atomicAdd(&d_cntin[col[e]], 1);
    }
}

// exclusive scan of d_cntin (65536) : chunked 1024
__global__ __launch_bounds__(1024) void k_scan1() {
    __shared__ int sh[1024];
    int t = threadIdx.x;
    int i = blockIdx.x * 1024 + t;
    int v = d_cntin[i];
    sh[t] = v;
    __syncthreads();
    #pragma unroll
    for (int o = 1; o < 1024; o <<= 1) {
        int tmp = (t >= o) ? sh[t - o] : 0;
        __syncthreads();
        sh[t] += tmp;
        __syncthreads();
    }
    d_cstart[i] = sh[t] - v;
    if (t == 1023) d_bsum[blockIdx.x] = sh[1023];
}

__global__ void k_scan2() {
    __shared__ int sh[64];
    int t = threadIdx.x;
    int v = d_bsum[t];
    sh[t] = v;
    __syncthreads();
    for (int o = 1; o < 64; o <<= 1) {
        int tmp = (t >= o) ? sh[t - o] : 0;
        __syncthreads();
        sh[t] += tmp;
        __syncthreads();
    }
    d_boff[t] = sh[t] - v;
}

__global__ void k_scan3() {
    int i = blockIdx.x * blockDim.x + threadIdx.x;
    if (i < NTOT) d_cstart[i] += d_boff[i >> 10];
}

__global__ void k_dinv(int n) {
    int i = blockIdx.x * blockDim.x + threadIdx.x;
    if (i < n) {
        float dg = (float)d_degi[i];
        d_dinv[i] = dg > 0.f ? rsqrtf(fmaxf(dg, 1.0f)) : 0.f;
    }
}

// fill buckets with EDGE IDS (order scrambled by atomics; sorted next)
__global__ void k_fill(const int* __restrict__ col, int E) {
    int e = blockIdx.x * blockDim.x + threadIdx.x;
    if (e < E) {
        int c = col[e];
        int pos = d_cstart[c] + atomicAdd(&d_cfill[c], 1);
        d_csr[pos] = e;
    }
}

// sort each bucket ascending by edge id (matches reference edge-order summation),
// replacing edge ids with source node ids. Warp per node, min-extraction.
__global__ void k_sort(const int* __restrict__ row) {
    int node = (blockIdx.x * blockDim.x + threadIdx.x) >> 5;
    int lane = threadIdx.x & 31;
    if (node >= NTOT) return;
    int beg = d_cstart[node], cnt = d_cntin[node];
    if (cnt == 0) return;
    if (cnt == 1) {
        if (lane == 0) d_csr[beg] = __ldg(&row[d_csr[beg]]);
        return;
    }
    if (cnt > 96) {   // fallback (never expected): just convert ids, unsorted
        for (int j = lane; j < cnt; j += 32)
            d_csr[beg + j] = __ldg(&row[d_csr[beg + j]]);
        return;
    }
    const int INF = 0x7fffffff;
    int v0 = (lane      < cnt) ? d_csr[beg + lane]      : INF;
    int v1 = (lane + 32 < cnt) ? d_csr[beg + lane + 32] : INF;
    int v2 = (lane + 64 < cnt) ? d_csr[beg + lane + 64] : INF;
    for (int k = 0; k < cnt; k++) {
        int m3 = min(v0, min(v1, v2));
        int g = m3;
        #pragma unroll
        for (int o = 16; o > 0; o >>= 1) g = min(g, __shfl_xor_sync(0xffffffffu, g, o));
        unsigned msk = __ballot_sync(0xffffffffu, m3 == g);
        int src = __ffs(msk) - 1;
        if (lane == src) {
            if (v0 == g) v0 = INF; else if (v1 == g) v1 = INF; else v2 = INF;
            d_csr[beg + k] = __ldg(&row[g]);
        }
    }
}

// ---------------- ChebConv gather (reference edge order, no FMA contraction) ----------------
__global__ void k_cheb_gather(const float* __restrict__ x) {
    int node = (blockIdx.x * blockDim.x + threadIdx.x) >> 5;
    int lane = threadIdx.x & 31;
    if (node >= NTOT) return;
    int beg = d_cstart[node], cnt = d_cntin[node];
    float dc = d_dinv[node];
    float4 acc = make_float4(0.f, 0.f, 0.f, 0.f);
    int r = (cnt > 0) ? __ldg(&d_csr[beg]) : 0;
    for (int j = 0; j < cnt; j++) {
        int rn = (j + 1 < cnt) ? __ldg(&d_csr[beg + j + 1]) : 0;   // pipeline next index
        float w = -(__ldg(&d_dinv[r]) * dc);           // w_e = -dinv[row]*dinv[col]
        float4 xv = *(const float4*)(x + r * IND + lane * 4);
        acc.x = __fadd_rn(acc.x, __fmul_rn(w, xv.x));
        acc.y = __fadd_rn(acc.y, __fmul_rn(w, xv.y));
        acc.z = __fadd_rn(acc.z, __fmul_rn(w, xv.z));
        acc.w = __fadd_rn(acc.w, __fmul_rn(w, xv.w));
        r = rn;
    }
    *(float4*)(d_tx1 + node * IND + lane * 4) = acc;
}

// ---------------- GEMMs : 128x64 block tile, 8x4 microtile, 256 thr ----------------
// h = relu(x@W0 + tx1@W1 + b) : K = 128(x) + 128(tx1), N=256
__global__ __launch_bounds__(256) void k_gemm_h(const float* __restrict__ x,
                                                const float* __restrict__ w0,
                                                const float* __restrict__ w1,
                                                const float* __restrict__ bias) {
    __shared__ float As[16][132];
    __shared__ float Bs[16][64];
    int tid = threadIdx.x;
    int tx = tid & 15, ty = tid >> 4;
    int m0 = blockIdx.y * 128, n0 = blockIdx.x * 64;
    float acc[8][4] = {};
    for (int k0 = 0; k0 < 256; k0 += 16) {
        {
            int r = tid >> 1, kq = (tid & 1) * 8;
            const float* base = (k0 < 128) ? (x + k0) : (d_tx1 + (k0 - 128));
            const float* src = base + (m0 + r) * IND + kq;
            float4 v0 = *(const float4*)(src);
            float4 v1 = *(const float4*)(src + 4);
            As[kq + 0][r] = v0.x; As[kq + 1][r] = v0.y;
            As[kq + 2][r] = v0.z; As[kq + 3][r] = v0.w;
            As[kq + 4][r] = v1.x; As[kq + 5][r] = v1.y;
            As[kq + 6][r] = v1.z; As[kq + 7][r] = v1.w;
        }
        {
            int kr = tid >> 4, nq = (tid & 15) * 4;
            int kk = k0 + kr;
            const float* src = (kk < 128) ? (w0 + kk * H1 + n0 + nq)
                                          : (w1 + (kk - 128) * H1 + n0 + nq);
            *(float4*)&Bs[kr][nq] = *(const float4*)src;
        }
        __syncthreads();
        #pragma unroll
        for (int kk = 0; kk < 16; kk++) {
            float4 a0 = *(float4*)&As[kk][ty * 8];
            float4 a1 = *(float4*)&As[kk][ty * 8 + 4];
            float4 b4 = *(float4*)&Bs[kk][tx * 4];
            float a[8] = {a0.x, a0.y, a0.z, a0.w, a1.x, a1.y, a1.z, a1.w};
            float b[4] = {b4.x, b4.y, b4.z, b4.w};
            #pragma unroll
            for (int i = 0; i < 8; i++)
                #pragma unroll
                for (int j = 0; j < 4; j++) acc[i][j] += a[i] * b[j];
        }
        __syncthreads();
    }
    float4 bv = *(const float4*)(bias + n0 + tx * 4);
    #pragma unroll
    for (int i = 0; i < 8; i++) {
        int m = m0 + ty * 8 + i;
        float4 o;
        o.x = fmaxf(acc[i][0] + bv.x, 0.f);
        o.y = fmaxf(acc[i][1] + bv.y, 0.f);
        o.z = fmaxf(acc[i][2] + bv.z, 0.f);
        o.w = fmaxf(acc[i][3] + bv.w, 0.f);
        *(float4*)(d_h + m * H1 + n0 + tx * 4) = o;
    }
}

// z = h @ gat_w : K=256, N=128
__global__ __launch_bounds__(256) void k_gemm_z(const float* __restrict__ w) {
    __shared__ float As[16][132];
    __shared__ float Bs[16][64];
    int tid = threadIdx.x;
    int tx = tid & 15, ty = tid >> 4;
    int m0 = blockIdx.y * 128, n0 = blockIdx.x * 64;
    float acc[8][4] = {};
    for (int k0 = 0; k0 < 256; k0 += 16) {
        {
            int r = tid >> 1, kq = (tid & 1) * 8;
            const float* src = d_h + (m0 + r) * H1 + k0 + kq;
            float4 v0 = *(const float4*)(src);
            float4 v1 = *(const float4*)(src + 4);
            As[kq + 0][r] = v0.x; As[kq + 1][r] = v0.y;
            As[kq + 2][r] = v0.z; As[kq + 3][r] = v0.w;
            As[kq + 4][r] = v1.x; As[kq + 5][r] = v1.y;
            As[kq + 6][r] = v1.z; As[kq + 7][r] = v1.w;
        }
        {
            int kr = tid >> 4, nq = (tid & 15) * 4;
            *(float4*)&Bs[kr][nq] = *(const float4*)(w + (k0 + kr) * H2 + n0 + nq);
        }
        __syncthreads();
        #pragma unroll
        for (int kk = 0; kk < 16; kk++) {
            float4 a0 = *(float4*)&As[kk][ty * 8];
            float4 a1 = *(float4*)&As[kk][ty * 8 + 4];
            float4 b4 = *(float4*)&Bs[kk][tx * 4];
            float a[8] = {a0.x, a0.y, a0.z, a0.w, a1.x, a1.y, a1.z, a1.w};
            float b[4] = {b4.x, b4.y, b4.z, b4.w};
            #pragma unroll
            for (int i = 0; i < 8; i++)
                #pragma unroll
                for (int j = 0; j < 4; j++) acc[i][j] += a[i] * b[j];
        }
        __syncthreads();
    }
    #pragma unroll
    for (int i = 0; i < 8; i++) {
        int m = m0 + ty * 8 + i;
        float4 o = make_float4(acc[i][0], acc[i][1], acc[i][2], acc[i][3]);
        *(float4*)(d_z + m * H2 + n0 + tx * 4) = o;
    }
}

// ---------------- attention coefficients ----------------
__global__ void k_attn_coef(const float* __restrict__ asrc, const float* __restrict__ adst, int n) {
    int i    = (blockIdx.x * blockDim.x + threadIdx.x) >> 5;
    int lane = threadIdx.x & 31;
    if (i >= n) return;
    float4 zv = *(const float4*)(d_z + i * H2 + lane * 4);
    float4 av = *(const float4*)(asrc + lane * 4);
    float4 bv = *(const float4*)(adst + lane * 4);
    float s = zv.x * av.x + zv.y * av.y + zv.z * av.z + zv.w * av.w;
    float d = zv.x * bv.x + zv.y * bv.y + zv.z * bv.z + zv.w * bv.w;
    #pragma unroll
    for (int o = 16; o > 0; o >>= 1) {
        s += __shfl_down_sync(0xffffffffu, s, o);
        d += __shfl_down_sync(0xffffffffu, d, o);
    }
    if (lane == 0) { d_as[i] = s; d_ad[i] = d; }
}

__global__ void k_pnorm(const float* __restrict__ p) {
    __shared__ float sh[128];
    int t = threadIdx.x;
    float v = p[t];
    sh[t] = v * v;
    __syncthreads();
    for (int o = 64; o > 0; o >>= 1) {
        if (t < o) sh[t] += sh[t + o];
        __syncthreads();
    }
    if (t == 0) d_invpnorm = 1.0f / sqrtf(sh[0]);
}

// ---------------- fused GAT softmax-aggregate + relu + score ----------------
// Reference arithmetic: p_e = expf(e - m); ssum edges-then-self;
// alpha = p_e / ssum; aggregate edges-then-self; no FMA contraction.
__global__ void k_gat(const float* __restrict__ gb, const float* __restrict__ p) {
    int node = (blockIdx.x * blockDim.x + threadIdx.x) >> 5;
    int lane = threadIdx.x & 31;
    if (node >= NTOT) return;
    int beg = d_cstart[node], cnt = d_cntin[node];
    float ad_c = d_ad[node];
    float eself = lrelu(d_as[node] + ad_c);
    // pass 1: segment max (exact, order-free)
    float m = eself;
    for (int j = lane; j < cnt; j += 32) {
        int r = __ldg(&d_csr[beg + j]);
        m = fmaxf(m, lrelu(__ldg(&d_as[r]) + ad_c));
    }
    #pragma unroll
    for (int o = 16; o > 0; o >>= 1) m = fmaxf(m, __shfl_xor_sync(0xffffffffu, m, o));
    // pass 2: ssum in edge order, self last
    float ssum = 0.f;
    for (int j = 0; j < cnt; j++) {
        int r = __ldg(&d_csr[beg + j]);
        ssum = __fadd_rn(ssum, expf(lrelu(__ldg(&d_as[r]) + ad_c) - m));
    }
    float pself = expf(eself - m);
    ssum = __fadd_rn(ssum, pself);
    // pass 3: aggregate alpha*z in edge order, self last
    float4 acc = make_float4(0.f, 0.f, 0.f, 0.f);
    int r = (cnt > 0) ? __ldg(&d_csr[beg]) : 0;
    for (int j = 0; j < cnt; j++) {
        int rn = (j + 1 < cnt) ? __ldg(&d_csr[beg + j + 1]) : 0;   // pipeline next index
        float alpha = expf(lrelu(__ldg(&d_as[r]) + ad_c) - m) / ssum;
        float4 zv = *(const float4*)(d_z + r * H2 + lane * 4);
        acc.x = __fadd_rn(acc.x, __fmul_rn(alpha, zv.x));
        acc.y = __fadd_rn(acc.y, __fmul_rn(alpha, zv.y));
        acc.z = __fadd_rn(acc.z, __fmul_rn(alpha, zv.z));
        acc.w = __fadd_rn(acc.w, __fmul_rn(alpha, zv.w));
        r = rn;
    }
    float aself = pself / ssum;
    float4 zc = *(const float4*)(d_z + node * H2 + lane * 4);
    float4 bv = *(const float4*)(gb + lane * 4);
    float4 g;
    g.x = fmaxf(__fadd_rn(acc.x, __fmul_rn(aself, zc.x)) + bv.x, 0.f);
    g.y = fmaxf(__fadd_rn(acc.y, __fmul_rn(aself, zc.y)) + bv.y, 0.f);
    g.z = fmaxf(__fadd_rn(acc.z, __fmul_rn(aself, zc.z)) + bv.z, 0.f);
    g.w = fmaxf(__fadd_rn(acc.w, __fmul_rn(aself, zc.w)) + bv.w, 0.f);
    *(float4*)(d_g + node * H2 + lane * 4) = g;
    float4 pv = *(const float4*)(p + lane * 4);
    float sc = g.x * pv.x + g.y * pv.y + g.z * pv.z + g.w * pv.w;
    #pragma unroll
    for (int o = 16; o > 0; o >>= 1) sc += __shfl_down_sync(0xffffffffu, sc, o);
    if (lane == 0) d_score[node] = tanhf(sc * d_invpnorm);
}

// ---------------- top-k pool (bitonic) + gated mean ----------------
__global__ __launch_bounds__(256) void k_topk_pool() {
    __shared__ float sv[NPG];
    __shared__ int   si[NPG];
    __shared__ float part[256];
    int b = blockIdx.x, t = threadIdx.x;
    int base = b * NPG;
    sv[t]       = d_score[base + t];       si[t]       = t;
    sv[t + 256] = d_score[base + t + 256]; si[t + 256] = t + 256;
    __syncthreads();
    for (int k = 2; k <= NPG; k <<= 1) {
        for (int j = k >> 1; j > 0; j >>= 1) {
            #pragma unroll
            for (int s = 0; s < 2; s++) {
                int i = t + s * 256;
                int ixj = i ^ j;
                if (ixj > i) {
                    bool up = ((i & k) == 0);
                    float vi = sv[i], vj = sv[ixj];
                    bool sw = up ? (vi < vj) : (vi > vj);
                    if (sw) {
                        sv[i] = vj; sv[ixj] = vi;
                        int ti = si[i]; si[i] = si[ixj]; si[ixj] = ti;
                    }
                }
            }
            __syncthreads();
        }
    }
    int d = t & 127, half = t >> 7;
    float acc = 0.f;
    for (int j = half * 128; j < half * 128 + 128; j++)
        acc += d_g[(base + si[j]) * H2 + d] * sv[j];
    part[t] = acc;
    __syncthreads();
    if (t < 128) d_gm[b * H2 + t] = (part[t] + part[t + 128]) * (1.0f / (float)KPOOL);
}

// ---------------- MLP head ----------------
__global__ __launch_bounds__(256) void k_mlp(const float* __restrict__ w1,
                                             const float* __restrict__ b1,
                                             const float* __restrict__ w2,
                                             const float* __restrict__ b2,
                                             float* __restrict__ out) {
    __shared__ float sgm[H2];
    __shared__ float red[256];
    int b = blockIdx.x, t = threadIdx.x;
    if (t < H2) sgm[t] = d_gm[b * H2 + t];
    __syncthreads();
    float acc = b1[t];
    #pragma unroll 8
    for (int k = 0; k < H2; k++) acc += sgm[k] * w1[k * H1 + t];
    red[t] = fmaxf(acc, 0.f) * w2[t];
    __syncthreads();
    for (int o = 128; o > 0; o >>= 1) {
        if (t < o) red[t] += red[t + o];
        __syncthreads();
    }
    if (t == 0) out[b] = red[0] + b2[0];
}

// ---------------- launch ----------------
extern "C" void kernel_launch(void* const* d_in, const int* in_sizes, int n_in,
                              void* d_out, int out_size) {
    const float* x     = (const float*)d_in[0];
    const int*   ei    = (const int*)  d_in[1];
    const float* cw0   = (const float*)d_in[3];
    const float* cw1   = (const float*)d_in[4];
    const float* cb    = (const float*)d_in[5];
    const float* gw    = (const float*)d_in[6];
    const float* gas   = (const float*)d_in[7];
    const float* gad   = (const float*)d_in[8];
    const float* gb    = (const float*)d_in[9];
    const float* pp    = (const float*)d_in[10];
    const float* l1w   = (const float*)d_in[11];
    const float* l1b   = (const float*)d_in[12];
    const float* l2w   = (const float*)d_in[13];
    const float* l2b   = (const float*)d_in[14];
    float* out = (float*)d_out;

    int n = in_sizes[0] / IND;          // 65536
    int E = in_sizes[1] / 2;            // 524288
    const int* row = ei;
    const int* col = ei + E;

    // CSR build (sorted buckets -> reference summation order)
    k_zero<<<(NTOT + 255) / 256, 256>>>();
    k_count<<<(E + 255) / 256, 256>>>(row, col, E);
    k_scan1<<<64, 1024>>>();
    k_scan2<<<1, 64>>>();
    k_scan3<<<(NTOT + 255) / 256, 256>>>();
    k_dinv<<<(n + 255) / 256, 256>>>(n);
    k_fill<<<(E + 255) / 256, 256>>>(col, E);
    k_sort<<<NTOT * 32 / 256, 256>>>(row);

    // ChebConv
    k_cheb_gather<<<NTOT * 32 / 256, 256>>>(x);
    dim3 gh(H1 / 64, NTOT / 128);
    k_gemm_h<<<gh, 256>>>(x, cw0, cw1, cb);

    // GAT
    dim3 gz(H2 / 64, NTOT / 128);
    k_gemm_z<<<gz, 256>>>(gw);
    k_attn_coef<<<(n * 32 + 255) / 256, 256>>>(gas, gad, n);
    k_pnorm<<<1, 128>>>(pp);
    k_gat<<<NTOT * 32 / 256, 256>>>(gb, pp);

    // Pool + head
    k_topk_pool<<<NGRAPH, 256>>>();
    k_mlp<<<NGRAPH, 256>>>(l1w, l1b, l2w, l2b, out);
}

// round 5
// speedup vs baseline: 1.5800x; 1.0034x over previous
#include <cuda_runtime.h>
#include <math.h>

#define NTOT   65536
#define NGRAPH 128
#define NPG    512
#define KPOOL  256
#define EDG    524288
#define IND    128
#define H1     256
#define H2     128

// ---------------- scratch (device globals; no allocation) ----------------
__device__ int      d_degi[NTOT];      // out-degree (row)
__device__ float    d_dinv[NTOT];
__device__ int      d_cntin[NTOT];     // in-degree (col)
__device__ int      d_cstart[NTOT];    // CSR row starts (by col)
__device__ int      d_cfill[NTOT];
__device__ int      d_bsum[64];
__device__ int      d_boff[64];
__device__ int      d_csr[EDG];        // edge ids -> (after sort) source node ids, by dst
__device__ float    d_tx1[NTOT * IND];
__device__ float    d_h  [NTOT * H1];
__device__ float    d_z  [NTOT * H2];
__device__ float    d_as [NTOT];
__device__ float    d_ad [NTOT];
__device__ float    d_g  [NTOT * H2];
__device__ float    d_score[NTOT];
__device__ float    d_gm [NGRAPH * H2];
__device__ float    d_invpnorm;

// ---------------- helpers ----------------
__device__ __forceinline__ float lrelu(float x) { return x > 0.f ? x : 0.2f * x; }

__device__ __forceinline__ void tf32_split(float x, unsigned& hi, unsigned& lo) {
    unsigned h;
    asm("cvt.rna.tf32.f32 %0, %1;" : "=r"(h) : "f"(x));
    float hf = __uint_as_float(h);
    float lf = __fsub_rn(x, hf);
    unsigned l;
    asm("cvt.rna.tf32.f32 %0, %1;" : "=r"(l) : "f"(lf));
    hi = h; lo = l;
}

__device__ __forceinline__ void mma_tf32(float4& d, const unsigned* a, const unsigned* b) {
    asm volatile(
        "mma.sync.aligned.m16n8k8.row.col.f32.tf32.tf32.f32 "
        "{%0,%1,%2,%3}, {%4,%5,%6,%7}, {%8,%9}, {%0,%1,%2,%3};\n"
        : "+f"(d.x), "+f"(d.y), "+f"(d.z), "+f"(d.w)
        : "r"(a[0]), "r"(a[1]), "r"(a[2]), "r"(a[3]), "r"(b[0]), "r"(b[1]));
}

// ---------------- CSR build ----------------
__global__ void k_zero() {
    int i = blockIdx.x * blockDim.x + threadIdx.x;
    if (i < NTOT) { d_degi[i] = 0; d_cntin[i] = 0; d_cfill[i] = 0; }
}

__global__ void k_count(const int* __restrict__ row, const int* __restrict__ col, int E) {
    int e = blockIdx.x * blockDim.x + threadIdx.x;
    if (e < E) {
        atomicAdd(&d_degi[row[e]], 1);
        atomicAdd(&d_cntin[col[e]], 1);
    }
}

// exclusive scan of d_cntin (65536) : chunked 1024
__global__ __launch_bounds__(1024) void k_scan1() {
    __shared__ int sh[1024];
    int t = threadIdx.x;
    int i = blockIdx.x * 1024 + t;
    int v = d_cntin[i];
    sh[t] = v;
    __syncthreads();
    #pragma unroll
    for (int o = 1; o < 1024; o <<= 1) {
        int tmp = (t >= o) ? sh[t - o] : 0;
        __syncthreads();
        sh[t] += tmp;
        __syncthreads();
    }
    d_cstart[i] = sh[t] - v;
    if (t == 1023) d_bsum[blockIdx.x] = sh[1023];
}

__global__ void k_scan2() {
    __shared__ int sh[64];
    int t = threadIdx.x;
    int v = d_bsum[t];
    sh[t] = v;
    __syncthreads();
    for (int o = 1; o < 64; o <<= 1) {
        int tmp = (t >= o) ? sh[t - o] : 0;
        __syncthreads();
        sh[t] += tmp;
        __syncthreads();
    }
    d_boff[t] = sh[t] - v;
}

__global__ void k_scan3() {
    int i = blockIdx.x * blockDim.x + threadIdx.x;
    if (i < NTOT) d_cstart[i] += d_boff[i >> 10];
}

__global__ void k_dinv(int n) {
    int i = blockIdx.x * blockDim.x + threadIdx.x;
    if (i < n) {
        float dg = (float)d_degi[i];
        d_dinv[i] = dg > 0.f ? rsqrtf(fmaxf(dg, 1.0f)) : 0.f;
    }
}

// fill buckets with EDGE IDS (order scrambled by atomics; sorted next)
__global__ void k_fill(const int* __restrict__ col, int E) {
    int e = blockIdx.x * blockDim.x + threadIdx.x;
    if (e < E) {
        int c = col[e];
        int pos = d_cstart[c] + atomicAdd(&d_cfill[c], 1);
        d_csr[pos] = e;
    }
}

// sort each bucket ascending by edge id (matches reference edge-order summation),
// replacing edge ids with source node ids. Warp per node, min-extraction.
__global__ void k_sort(const int* __restrict__ row) {
    int node = (blockIdx.x * blockDim.x + threadIdx.x) >> 5;
    int lane = threadIdx.x & 31;
    if (node >= NTOT) return;
    int beg = d_cstart[node], cnt = d_cntin[node];
    if (cnt == 0) return;
    if (cnt == 1) {
        if (lane == 0) d_csr[beg] = __ldg(&row[d_csr[beg]]);
        return;
    }
    if (cnt > 96) {   // fallback (never expected): just convert ids, unsorted
        for (int j = lane; j < cnt; j += 32)
            d_csr[beg + j] = __ldg(&row[d_csr[beg + j]]);
        return;
    }
    const int INF = 0x7fffffff;
    int v0 = (lane      < cnt) ? d_csr[beg + lane]      : INF;
    int v1 = (lane + 32 < cnt) ? d_csr[beg + lane + 32] : INF;
    int v2 = (lane + 64 < cnt) ? d_csr[beg + lane + 64] : INF;
    for (int k = 0; k < cnt; k++) {
        int m3 = min(v0, min(v1, v2));
        int g = m3;
        #pragma unroll
        for (int o = 16; o > 0; o >>= 1) g = min(g, __shfl_xor_sync(0xffffffffu, g, o));
        unsigned msk = __ballot_sync(0xffffffffu, m3 == g);
        int src = __ffs(msk) - 1;
        if (lane == src) {
            if (v0 == g) v0 = INF; else if (v1 == g) v1 = INF; else v2 = INF;
            d_csr[beg + k] = __ldg(&row[g]);
        }
    }
}

// ---------------- ChebConv gather (reference edge order, no FMA contraction) ----------------
__global__ void k_cheb_gather(const float* __restrict__ x) {
    int node = (blockIdx.x * blockDim.x + threadIdx.x) >> 5;
    int lane = threadIdx.x & 31;
    if (node >= NTOT) return;
    int beg = d_cstart[node], cnt = d_cntin[node];
    float dc = d_dinv[node];
    float4 acc = make_float4(0.f, 0.f, 0.f, 0.f);
    int r = (cnt > 0) ? __ldg(&d_csr[beg]) : 0;
    for (int j = 0; j < cnt; j++) {
        int rn = (j + 1 < cnt) ? __ldg(&d_csr[beg + j + 1]) : 0;   // pipeline next index
        float w = -(__ldg(&d_dinv[r]) * dc);           // w_e = -dinv[row]*dinv[col]
        float4 xv = *(const float4*)(x + r * IND + lane * 4);
        acc.x = __fadd_rn(acc.x, __fmul_rn(w, xv.x));
        acc.y = __fadd_rn(acc.y, __fmul_rn(w, xv.y));
        acc.z = __fadd_rn(acc.z, __fmul_rn(w, xv.z));
        acc.w = __fadd_rn(acc.w, __fmul_rn(w, xv.w));
        r = rn;
    }
    *(float4*)(d_tx1 + node * IND + lane * 4) = acc;
}

// ---------------- tensor-core GEMMs : 3xTF32 split, m16n8k8 mma ----------------
// Block tile 128(M) x 64(N), kstep 16, 8 warps as 4(m) x 2(n), warp tile 32x32.
// h = relu(x@W0 + tx1@W1 + b) : K = 128(x) + 128(tx1), N=256
__global__ __launch_bounds__(256) void k_gemm_h_tc(const float* __restrict__ x,
                                                   const float* __restrict__ w0,
                                                   const float* __restrict__ w1,
                                                   const float* __restrict__ bias) {
    __shared__ unsigned Ah[16][136], Al[16][136];
    __shared__ unsigned Bh[16][72],  Bl[16][72];
    int tid = threadIdx.x;
    int lane = tid & 31, wid = tid >> 5;
    int warp_m = wid & 3, warp_n = wid >> 2;
    int m0 = blockIdx.y * 128, n0 = blockIdx.x * 64;
    float4 dacc[2][4];
    #pragma unroll
    for (int i = 0; i < 2; i++)
        #pragma unroll
        for (int j = 0; j < 4; j++) dacc[i][j] = make_float4(0.f, 0.f, 0.f, 0.f);

    for (int k0 = 0; k0 < 256; k0 += 16) {
        {   // A tile: 128 rows x 16 k ; thread loads 8 consecutive k for one row
            int r = tid >> 1, kq = (tid & 1) * 8;
            const float* base = (k0 < 128) ? (x + k0) : (d_tx1 + (k0 - 128));
            const float* src = base + (m0 + r) * IND + kq;
            float4 v0 = *(const float4*)(src);
            float4 v1 = *(const float4*)(src + 4);
            float v[8] = {v0.x, v0.y, v0.z, v0.w, v1.x, v1.y, v1.z, v1.w};
            #pragma unroll
            for (int i = 0; i < 8; i++) tf32_split(v[i], Ah[kq + i][r], Al[kq + i][r]);
        }
        {   // B tile: 16 k x 64 n
            int kr = tid >> 4, nq = (tid & 15) * 4;
            int kk = k0 + kr;
            const float* src = (kk < 128) ? (w0 + kk * H1 + n0 + nq)
                                          : (w1 + (kk - 128) * H1 + n0 + nq);
            float4 bv = *(const float4*)src;
            float v[4] = {bv.x, bv.y, bv.z, bv.w};
            #pragma unroll
            for (int i = 0; i < 4; i++) tf32_split(v[i], Bh[kr][nq + i], Bl[kr][nq + i]);
        }
        __syncthreads();
        #pragma unroll
        for (int ks = 0; ks < 16; ks += 8) {
            unsigned ah[2][4], al[2][4], bh[4][2], bl[4][2];
            int kr = ks + (lane & 3);
            int mr = warp_m * 32 + (lane >> 2);
            #pragma unroll
            for (int tm = 0; tm < 2; tm++) {
                int m = mr + tm * 16;
                ah[tm][0] = Ah[kr][m];     ah[tm][1] = Ah[kr][m + 8];
                ah[tm][2] = Ah[kr + 4][m]; ah[tm][3] = Ah[kr + 4][m + 8];
                al[tm][0] = Al[kr][m];     al[tm][1] = Al[kr][m + 8];
                al[tm][2] = Al[kr + 4][m]; al[tm][3] = Al[kr + 4][m + 8];
            }
            int nc = warp_n * 32 + (lane >> 2);
            #pragma unroll
            for (int tn = 0; tn < 4; tn++) {
                int nn = nc + tn * 8;
                bh[tn][0] = Bh[kr][nn]; bh[tn][1] = Bh[kr + 4][nn];
                bl[tn][0] = Bl[kr][nn]; bl[tn][1] = Bl[kr + 4][nn];
            }
            #pragma unroll
            for (int tm = 0; tm < 2; tm++)
                #pragma unroll
                for (int tn = 0; tn < 4; tn++) {
                    mma_tf32(dacc[tm][tn], ah[tm], bh[tn]);
                    mma_tf32(dacc[tm][tn], ah[tm], bl[tn]);
                    mma_tf32(dacc[tm][tn], al[tm], bh[tn]);
                }
        }
        __syncthreads();
    }
    #pragma unroll
    for (int tm = 0; tm < 2; tm++) {
        int rr = m0 + warp_m * 32 + tm * 16 + (lane >> 2);
        #pragma unroll
        for (int tn = 0; tn < 4; tn++) {
            int cc = n0 + warp_n * 32 + tn * 8 + (lane & 3) * 2;
            float bx = bias[cc], by = bias[cc + 1];
            float4 d = dacc[tm][tn];
            *(float2*)(d_h + rr * H1 + cc) =
                make_float2(fmaxf(d.x + bx, 0.f), fmaxf(d.y + by, 0.f));
            *(float2*)(d_h + (rr + 8) * H1 + cc) =
                make_float2(fmaxf(d.z + bx, 0.f), fmaxf(d.w + by, 0.f));
        }
    }
}

// z = h @ gat_w : K=256, N=128
__global__ __launch_bounds__(256) void k_gemm_z_tc(const float* __restrict__ w) {
    __shared__ unsigned Ah[16][136], Al[16][136];
    __shared__ unsigned Bh[16][72],  Bl[16][72];
    int tid = threadIdx.x;
    int lane = tid & 31, wid = tid >> 5;
    int warp_m = wid & 3, warp_n = wid >> 2;
    int m0 = blockIdx.y * 128, n0 = blockIdx.x * 64;
    float4 dacc[2][4];
    #pragma unroll
    for (int i = 0; i < 2; i++)
        #pragma unroll
        for (int j = 0; j < 4; j++) dacc[i][j] = make_float4(0.f, 0.f, 0.f, 0.f);

    for (int k0 = 0; k0 < 256; k0 += 16) {
        {
            int r = tid >> 1, kq = (tid & 1) * 8;
            const float* src = d_h + (m0 + r) * H1 + k0 + kq;
            float4 v0 = *(const float4*)(src);
            float4 v1 = *(const float4*)(src + 4);
            float v[8] = {v0.x, v0.y, v0.z, v0.w, v1.x, v1.y, v1.z, v1.w};
            #pragma unroll
            for (int i = 0; i < 8; i++) tf32_split(v[i], Ah[kq + i][r], Al[kq + i][r]);
        }
        {
            int kr = tid >> 4, nq = (tid & 15) * 4;
            float4 bv = *(const float4*)(w + (k0 + kr) * H2 + n0 + nq);
            float v[4] = {bv.x, bv.y, bv.z, bv.w};
            #pragma unroll
            for (int i = 0; i < 4; i++) tf32_split(v[i], Bh[kr][nq + i], Bl[kr][nq + i]);
        }
        __syncthreads();
        #pragma unroll
        for (int ks = 0; ks < 16; ks += 8) {
            unsigned ah[2][4], al[2][4], bh[4][2], bl[4][2];
            int kr = ks + (lane & 3);
            int mr = warp_m * 32 + (lane >> 2);
            #pragma unroll
            for (int tm = 0; tm < 2; tm++) {
                int m = mr + tm * 16;
                ah[tm][0] = Ah[kr][m];     ah[tm][1] = Ah[kr][m + 8];
                ah[tm][2] = Ah[kr + 4][m]; ah[tm][3] = Ah[kr + 4][m + 8];
                al[tm][0] = Al[kr][m];     al[tm][1] = Al[kr][m + 8];
                al[tm][2] = Al[kr + 4][m]; al[tm][3] = Al[kr + 4][m + 8];
            }
            int nc = warp_n * 32 + (lane >> 2);
            #pragma unroll
            for (int tn = 0; tn < 4; tn++) {
                int nn = nc + tn * 8;
                bh[tn][0] = Bh[kr][nn]; bh[tn][1] = Bh[kr + 4][nn];
                bl[tn][0] = Bl[kr][nn]; bl[tn][1] = Bl[kr + 4][nn];
            }
            #pragma unroll
            for (int tm = 0; tm < 2; tm++)
                #pragma unroll
                for (int tn = 0; tn < 4; tn++) {
                    mma_tf32(dacc[tm][tn], ah[tm], bh[tn]);
                    mma_tf32(dacc[tm][tn], ah[tm], bl[tn]);
                    mma_tf32(dacc[tm][tn], al[tm], bh[tn]);
                }
        }
        __syncthreads();
    }
    #pragma unroll
    for (int tm = 0; tm < 2; tm++) {
        int rr = m0 + warp_m * 32 + tm * 16 + (lane >> 2);
        #pragma unroll
        for (int tn = 0; tn < 4; tn++) {
            int cc = n0 + warp_n * 32 + tn * 8 + (lane & 3) * 2;
            float4 d = dacc[tm][tn];
            *(float2*)(d_z + rr * H2 + cc)       = make_float2(d.x, d.y);
            *(float2*)(d_z + (rr + 8) * H2 + cc) = make_float2(d.z, d.w);
        }
    }
}

// ---------------- attention coefficients ----------------
__global__ void k_attn_coef(const float* __restrict__ asrc, const float* __restrict__ adst, int n) {
    int i    = (blockIdx.x * blockDim.x + threadIdx.x) >> 5;
    int lane = threadIdx.x & 31;
    if (i >= n) return;
    float4 zv = *(const float4*)(d_z + i * H2 + lane * 4);
    float4 av = *(const float4*)(asrc + lane * 4);
    float4 bv = *(const float4*)(adst + lane * 4);
    float s = zv.x * av.x + zv.y * av.y + zv.z * av.z + zv.w * av.w;
    float d = zv.x * bv.x + zv.y * bv.y + zv.z * bv.z + zv.w * bv.w;
    #pragma unroll
    for (int o = 16; o > 0; o >>= 1) {
        s += __shfl_down_sync(0xffffffffu, s, o);
        d += __shfl_down_sync(0xffffffffu, d, o);
    }
    if (lane == 0) { d_as[i] = s; d_ad[i] = d; }
}

__global__ void k_pnorm(const float* __restrict__ p) {
    __shared__ float sh[128];
    int t = threadIdx.x;
    float v = p[t];
    sh[t] = v * v;
    __syncthreads();
    for (int o = 64; o > 0; o >>= 1) {
        if (t < o) sh[t] += sh[t + o];
        __syncthreads();
    }
    if (t == 0) d_invpnorm = 1.0f / sqrtf(sh[0]);
}

// ---------------- fused GAT softmax-aggregate + relu + score ----------------
__global__ void k_gat(const float* __restrict__ gb, const float* __restrict__ p) {
    int node = (blockIdx.x * blockDim.x + threadIdx.x) >> 5;
    int lane = threadIdx.x & 31;
    if (node >= NTOT) return;
    int beg = d_cstart[node], cnt = d_cntin[node];
    float ad_c = d_ad[node];
    float eself = lrelu(d_as[node] + ad_c);
    // pass 1: segment max (exact, order-free)
    float m = eself;
    for (int j = lane; j < cnt; j += 32) {
        int r = __ldg(&d_csr[beg + j]);
        m = fmaxf(m, lrelu(__ldg(&d_as[r]) + ad_c));
    }
    #pragma unroll
    for (int o = 16; o > 0; o >>= 1) m = fmaxf(m, __shfl_xor_sync(0xffffffffu, m, o));
    // pass 2: ssum in edge order, self last
    float ssum = 0.f;
    for (int j = 0; j < cnt; j++) {
        int r = __ldg(&d_csr[beg + j]);
        ssum = __fadd_rn(ssum, expf(lrelu(__ldg(&d_as[r]) + ad_c) - m));
    }
    float pself = expf(eself - m);
    ssum = __fadd_rn(ssum, pself);
    // pass 3: aggregate alpha*z in edge order, self last
    float4 acc = make_float4(0.f, 0.f, 0.f, 0.f);
    int r = (cnt > 0) ? __ldg(&d_csr[beg]) : 0;
    for (int j = 0; j < cnt; j++) {
        int rn = (j + 1 < cnt) ? __ldg(&d_csr[beg + j + 1]) : 0;   // pipeline next index
        float alpha = expf(lrelu(__ldg(&d_as[r]) + ad_c) - m) / ssum;
        float4 zv = *(const float4*)(d_z + r * H2 + lane * 4);
        acc.x = __fadd_rn(acc.x, __fmul_rn(alpha, zv.x));
        acc.y = __fadd_rn(acc.y, __fmul_rn(alpha, zv.y));
        acc.z = __fadd_rn(acc.z, __fmul_rn(alpha, zv.z));
        acc.w = __fadd_rn(acc.w, __fmul_rn(alpha, zv.w));
        r = rn;
    }
    float aself = pself / ssum;
    float4 zc = *(const float4*)(d_z + node * H2 + lane * 4);
    float4 bv = *(const float4*)(gb + lane * 4);
    float4 g;
    g.x = fmaxf(__fadd_rn(acc.x, __fmul_rn(aself, zc.x)) + bv.x, 0.f);
    g.y = fmaxf(__fadd_rn(acc.y, __fmul_rn(aself, zc.y)) + bv.y, 0.f);
    g.z = fmaxf(__fadd_rn(acc.z, __fmul_rn(aself, zc.z)) + bv.z, 0.f);
    g.w = fmaxf(__fadd_rn(acc.w, __fmul_rn(aself, zc.w)) + bv.w, 0.f);
    *(float4*)(d_g + node * H2 + lane * 4) = g;
    float4 pv = *(const float4*)(p + lane * 4);
    float sc = g.x * pv.x + g.y * pv.y + g.z * pv.z + g.w * pv.w;
    #pragma unroll
    for (int o = 16; o > 0; o >>= 1) sc += __shfl_down_sync(0xffffffffu, sc, o);
    if (lane == 0) d_score[node] = tanhf(sc * d_invpnorm);
}

// ---------------- top-k pool (bitonic) + gated mean ----------------
__global__ __launch_bounds__(256) void k_topk_pool() {
    __shared__ float sv[NPG];
    __shared__ int   si[NPG];
    __shared__ float part[256];
    int b = blockIdx.x, t = threadIdx.x;
    int base = b * NPG;
    sv[t]       = d_score[base + t];       si[t]       = t;
    sv[t + 256] = d_score[base + t + 256]; si[t + 256] = t + 256;
    __syncthreads();
    for (int k = 2; k <= NPG; k <<= 1) {
        for (int j = k >> 1; j > 0; j >>= 1) {
            #pragma unroll
            for (int s = 0; s < 2; s++) {
                int i = t + s * 256;
                int ixj = i ^ j;
                if (ixj > i) {
                    bool up = ((i & k) == 0);
                    float vi = sv[i], vj = sv[ixj];
                    bool sw = up ? (vi < vj) : (vi > vj);
                    if (sw) {
                        sv[i] = vj; sv[ixj] = vi;
                        int ti = si[i]; si[i] = si[ixj]; si[ixj] = ti;
                    }
                }
            }
            __syncthreads();
        }
    }
    int d = t & 127, half = t >> 7;
    float acc = 0.f;
    for (int j = half * 128; j < half * 128 + 128; j++)
        acc += d_g[(base + si[j]) * H2 + d] * sv[j];
    part[t] = acc;
    __syncthreads();
    if (t < 128) d_gm[b * H2 + t] = (part[t] + part[t + 128]) * (1.0f / (float)KPOOL);
}

// ---------------- MLP head ----------------
__global__ __launch_bounds__(256) void k_mlp(const float* __restrict__ w1,
                                             const float* __restrict__ b1,
                                             const float* __restrict__ w2,
                                             const float* __restrict__ b2,
                                             float* __restrict__ out) {
    __shared__ float sgm[H2];
    __shared__ float red[256];
    int b = blockIdx.x, t = threadIdx.x;
    if (t < H2) sgm[t] = d_gm[b * H2 + t];
    __syncthreads();
    float acc = b1[t];
    #pragma unroll 8
    for (int k = 0; k < H2; k++) acc += sgm[k] * w1[k * H1 + t];
    red[t] = fmaxf(acc, 0.f) * w2[t];
    __syncthreads();
    for (int o = 128; o > 0; o >>= 1) {
        if (t < o) red[t] += red[t + o];
        __syncthreads();
    }
    if (t == 0) out[b] = red[0] + b2[0];
}

// ---------------- launch ----------------
extern "C" void kernel_launch(void* const* d_in, const int* in_sizes, int n_in,
                              void* d_out, int out_size) {
    const float* x     = (const float*)d_in[0];
    const int*   ei    = (const int*)  d_in[1];
    const float* cw0   = (const float*)d_in[3];
    const float* cw1   = (const float*)d_in[4];
    const float* cb    = (const float*)d_in[5];
    const float* gw    = (const float*)d_in[6];
    const float* gas   = (const float*)d_in[7];
    const float* gad   = (const float*)d_in[8];
    const float* gb    = (const float*)d_in[9];
    const float* pp    = (const float*)d_in[10];
    const float* l1w   = (const float*)d_in[11];
    const float* l1b   = (const float*)d_in[12];
    const float* l2w   = (const float*)d_in[13];
    const float* l2b   = (const float*)d_in[14];
    float* out = (float*)d_out;

    int n = in_sizes[0] / IND;          // 65536
    int E = in_sizes[1] / 2;            // 524288
    const int* row = ei;
    const int* col = ei + E;

    // CSR build (sorted buckets -> reference summation order)
    k_zero<<<(NTOT + 255) / 256, 256>>>();
    k_count<<<(E + 255) / 256, 256>>>(row, col, E);
    k_scan1<<<64, 1024>>>();
    k_scan2<<<1, 64>>>();
    k_scan3<<<(NTOT + 255) / 256, 256>>>();
    k_dinv<<<(n + 255) / 256, 256>>>(n);
    k_fill<<<(E + 255) / 256, 256>>>(col, E);
    k_sort<<<NTOT * 32 / 256, 256>>>(row);

    // ChebConv
    k_cheb_gather<<<NTOT * 32 / 256, 256>>>(x);
    dim3 gh(H1 / 64, NTOT / 128);
    k_gemm_h_tc<<<gh, 256>>>(x, cw0, cw1, cb);

    // GAT
    dim3 gz(H2 / 64, NTOT / 128);
    k_gemm_z_tc<<<gz, 256>>>(gw);
    k_attn_coef<<<(n * 32 + 255) / 256, 256>>>(gas, gad, n);
    k_pnorm<<<1, 128>>>(pp);
    k_gat<<<NTOT * 32 / 256, 256>>>(gb, pp);

    // Pool + head
    k_topk_pool<<<NGRAPH, 256>>>();
    k_mlp<<<NGRAPH, 256>>>(l1w, l1b, l2w, l2b, out);
}

// round 6
// speedup vs baseline: 1.7436x; 1.1036x over previous
#include <cuda_runtime.h>
#include <math.h>

#define NTOT   65536
#define NGRAPH 128
#define NPG    512
#define EPG    4096
#define KPOOL  256
#define EDG    524288
#define IND    128
#define H1     256
#define H2     128

// ---------------- scratch (device globals; no allocation) ----------------
__device__ float    d_dinv[NTOT];
__device__ int      d_cntin[NTOT];     // in-degree (col)
__device__ int      d_cstart[NTOT];    // CSR bucket starts (global edge offsets)
__device__ int      d_csr[EDG];        // source node ids, grouped by dst, edge-ascending
__device__ float    d_tx1[NTOT * IND];
__device__ float    d_h  [NTOT * H1];
__device__ float    d_z  [NTOT * H2];
__device__ float    d_as [NTOT];
__device__ float    d_ad [NTOT];
__device__ float    d_g  [NTOT * H2];
__device__ float    d_score[NTOT];
__device__ float    d_gm [NGRAPH * H2];
__device__ float    d_invpnorm;

// ---------------- helpers ----------------
__device__ __forceinline__ float lrelu(float x) { return x > 0.f ? x : 0.2f * x; }

__device__ __forceinline__ void tf32_split(float x, unsigned& hi, unsigned& lo) {
    unsigned h;
    asm("cvt.rna.tf32.f32 %0, %1;" : "=r"(h) : "f"(x));
    float hf = __uint_as_float(h);
    float lf = __fsub_rn(x, hf);
    unsigned l;
    asm("cvt.rna.tf32.f32 %0, %1;" : "=r"(l) : "f"(lf));
    hi = h; lo = l;
}

__device__ __forceinline__ void mma_tf32(float4& d, const unsigned* a, const unsigned* b) {
    asm volatile(
        "mma.sync.aligned.m16n8k8.row.col.f32.tf32.tf32.f32 "
        "{%0,%1,%2,%3}, {%4,%5,%6,%7}, {%8,%9}, {%0,%1,%2,%3};\n"
        : "+f"(d.x), "+f"(d.y), "+f"(d.z), "+f"(d.w)
        : "r"(a[0]), "r"(a[1]), "r"(a[2]), "r"(a[3]), "r"(b[0]), "r"(b[1]));
}

// ---------------- fused per-graph CSR build ----------------
// One block (512 threads) per graph. Edges of graph b are [b*4096,(b+1)*4096),
// nodes [b*512,(b+1)*512). Produces: d_dinv, d_cntin, d_cstart, and d_csr with
// each destination bucket listing SOURCE node ids in ascending-edge-id order
// (exact reference segment-sum order; identical to the R4/R5 sorted CSR).
__global__ __launch_bounds__(512) void k_build(const int* __restrict__ row,
                                               const int* __restrict__ col) {
    __shared__ int sedge[EPG];     // (col_local<<16) | row_local
    __shared__ int sbuck[EPG];     // (e_local<<9) | row_local, per-bucket
    __shared__ int scnt[NPG];
    __shared__ int sdeg[NPG];
    __shared__ int sexcl[NPG];
    __shared__ int sfill[NPG];
    int b = blockIdx.x, t = threadIdx.x;
    int ebase = b * EPG, nbase = b * NPG;

    scnt[t] = 0; sdeg[t] = 0; sfill[t] = 0;
    __syncthreads();

    #pragma unroll
    for (int i = 0; i < EPG / NPG; i++) {
        int e = t + i * NPG;
        int rl = row[ebase + e] - nbase;
        int cl = col[ebase + e] - nbase;
        sedge[e] = (cl << 16) | rl;
        atomicAdd(&scnt[cl], 1);
        atomicAdd(&sdeg[rl], 1);
    }
    __syncthreads();

    // inclusive scan of scnt -> sexcl, then convert to exclusive
    int v = scnt[t];
    sexcl[t] = v;
    __syncthreads();
    for (int o = 1; o < NPG; o <<= 1) {
        int tmp = (t >= o) ? sexcl[t - o] : 0;
        __syncthreads();
        sexcl[t] += tmp;
        __syncthreads();
    }
    int excl = sexcl[t] - v;
    __syncthreads();
    sexcl[t] = excl;

    d_cstart[nbase + t] = ebase + excl;
    d_cntin[nbase + t]  = v;
    float dg = (float)sdeg[t];
    d_dinv[nbase + t] = dg > 0.f ? rsqrtf(fmaxf(dg, 1.0f)) : 0.f;
    __syncthreads();

    // fill buckets (order scrambled by atomics, fixed by per-bucket sort)
    #pragma unroll
    for (int i = 0; i < EPG / NPG; i++) {
        int e = t + i * NPG;
        int pv = sedge[e];
        int cl = pv >> 16;
        int pos = atomicAdd(&sfill[cl], 1);
        sbuck[sexcl[cl] + pos] = (e << 9) | (pv & 511);
    }
    __syncthreads();

    // per-node insertion sort by edge id (high bits), then emit global row ids
    int beg = sexcl[t], cnt = scnt[t];
    for (int i = beg + 1; i < beg + cnt; i++) {
        int key = sbuck[i];
        int j = i - 1;
        while (j >= beg && sbuck[j] > key) { sbuck[j + 1] = sbuck[j]; j--; }
        sbuck[j + 1] = key;
    }
    for (int j = 0; j < cnt; j++)
        d_csr[ebase + beg + j] = nbase + (sbuck[beg + j] & 511);
}

// ---------------- ChebConv gather (reference edge order, no FMA contraction) ----------------
__global__ void k_cheb_gather(const float* __restrict__ x) {
    int node = (blockIdx.x * blockDim.x + threadIdx.x) >> 5;
    int lane = threadIdx.x & 31;
    if (node >= NTOT) return;
    int beg = d_cstart[node], cnt = d_cntin[node];
    float dc = d_dinv[node];
    float4 acc = make_float4(0.f, 0.f, 0.f, 0.f);
    int r = (cnt > 0) ? __ldg(&d_csr[beg]) : 0;
    for (int j = 0; j < cnt; j++) {
        int rn = (j + 1 < cnt) ? __ldg(&d_csr[beg + j + 1]) : 0;   // pipeline next index
        float w = -(__ldg(&d_dinv[r]) * dc);           // w_e = -dinv[row]*dinv[col]
        float4 xv = *(const float4*)(x + r * IND + lane * 4);
        acc.x = __fadd_rn(acc.x, __fmul_rn(w, xv.x));
        acc.y = __fadd_rn(acc.y, __fmul_rn(w, xv.y));
        acc.z = __fadd_rn(acc.z, __fmul_rn(w, xv.z));
        acc.w = __fadd_rn(acc.w, __fmul_rn(w, xv.w));
        r = rn;
    }
    *(float4*)(d_tx1 + node * IND + lane * 4) = acc;
}

// ---------------- tensor-core GEMMs : 3xTF32 split, m16n8k8 mma ----------------
// h = relu(x@W0 + tx1@W1 + b) : K = 128(x) + 128(tx1), N=256
__global__ __launch_bounds__(256) void k_gemm_h_tc(const float* __restrict__ x,
                                                   const float* __restrict__ w0,
                                                   const float* __restrict__ w1,
                                                   const float* __restrict__ bias) {
    __shared__ unsigned Ah[16][136], Al[16][136];
    __shared__ unsigned Bh[16][72],  Bl[16][72];
    int tid = threadIdx.x;
    int lane = tid & 31, wid = tid >> 5;
    int warp_m = wid & 3, warp_n = wid >> 2;
    int m0 = blockIdx.y * 128, n0 = blockIdx.x * 64;
    float4 dacc[2][4];
    #pragma unroll
    for (int i = 0; i < 2; i++)
        #pragma unroll
        for (int j = 0; j < 4; j++) dacc[i][j] = make_float4(0.f, 0.f, 0.f, 0.f);

    for (int k0 = 0; k0 < 256; k0 += 16) {
        {   // A tile: 128 rows x 16 k ; thread loads 8 consecutive k for one row
            int r = tid >> 1, kq = (tid & 1) * 8;
            const float* base = (k0 < 128) ? (x + k0) : (d_tx1 + (k0 - 128));
            const float* src = base + (m0 + r) * IND + kq;
            float4 v0 = *(const float4*)(src);
            float4 v1 = *(const float4*)(src + 4);
            float v[8] = {v0.x, v0.y, v0.z, v0.w, v1.x, v1.y, v1.z, v1.w};
            #pragma unroll
            for (int i = 0; i < 8; i++) tf32_split(v[i], Ah[kq + i][r], Al[kq + i][r]);
        }
        {   // B tile: 16 k x 64 n
            int kr = tid >> 4, nq = (tid & 15) * 4;
            int kk = k0 + kr;
            const float* src = (kk < 128) ? (w0 + kk * H1 + n0 + nq)
                                          : (w1 + (kk - 128) * H1 + n0 + nq);
            float4 bv = *(const float4*)src;
            float v[4] = {bv.x, bv.y, bv.z, bv.w};
            #pragma unroll
            for (int i = 0; i < 4; i++) tf32_split(v[i], Bh[kr][nq + i], Bl[kr][nq + i]);
        }
        __syncthreads();
        #pragma unroll
        for (int ks = 0; ks < 16; ks += 8) {
            unsigned ah[2][4], al[2][4], bh[4][2], bl[4][2];
            int kr = ks + (lane & 3);
            int mr = warp_m * 32 + (lane >> 2);
            #pragma unroll
            for (int tm = 0; tm < 2; tm++) {
                int m = mr + tm * 16;
                ah[tm][0] = Ah[kr][m];     ah[tm][1] = Ah[kr][m + 8];
                ah[tm][2] = Ah[kr + 4][m]; ah[tm][3] = Ah[kr + 4][m + 8];
                al[tm][0] = Al[kr][m];     al[tm][1] = Al[kr][m + 8];
                al[tm][2] = Al[kr + 4][m]; al[tm][3] = Al[kr + 4][m + 8];
            }
            int nc = warp_n * 32 + (lane >> 2);
            #pragma unroll
            for (int tn = 0; tn < 4; tn++) {
                int nn = nc + tn * 8;
                bh[tn][0] = Bh[kr][nn]; bh[tn][1] = Bh[kr + 4][nn];
                bl[tn][0] = Bl[kr][nn]; bl[tn][1] = Bl[kr + 4][nn];
            }
            #pragma unroll
            for (int tm = 0; tm < 2; tm++)
                #pragma unroll
                for (int tn = 0; tn < 4; tn++) {
                    mma_tf32(dacc[tm][tn], ah[tm], bh[tn]);
                    mma_tf32(dacc[tm][tn], ah[tm], bl[tn]);
                    mma_tf32(dacc[tm][tn], al[tm], bh[tn]);
                }
        }
        __syncthreads();
    }
    #pragma unroll
    for (int tm = 0; tm < 2; tm++) {
        int rr = m0 + warp_m * 32 + tm * 16 + (lane >> 2);
        #pragma unroll
        for (int tn = 0; tn < 4; tn++) {
            int cc = n0 + warp_n * 32 + tn * 8 + (lane & 3) * 2;
            float bx = bias[cc], by = bias[cc + 1];
            float4 d = dacc[tm][tn];
            *(float2*)(d_h + rr * H1 + cc) =
                make_float2(fmaxf(d.x + bx, 0.f), fmaxf(d.y + by, 0.f));
            *(float2*)(d_h + (rr + 8) * H1 + cc) =
                make_float2(fmaxf(d.z + bx, 0.f), fmaxf(d.w + by, 0.f));
        }
    }
}

// z = h @ gat_w : K=256, N=128
__global__ __launch_bounds__(256) void k_gemm_z_tc(const float* __restrict__ w) {
    __shared__ unsigned Ah[16][136], Al[16][136];
    __shared__ unsigned Bh[16][72],  Bl[16][72];
    int tid = threadIdx.x;
    int lane = tid & 31, wid = tid >> 5;
    int warp_m = wid & 3, warp_n = wid >> 2;
    int m0 = blockIdx.y * 128, n0 = blockIdx.x * 64;
    float4 dacc[2][4];
    #pragma unroll
    for (int i = 0; i < 2; i++)
        #pragma unroll
        for (int j = 0; j < 4; j++) dacc[i][j] = make_float4(0.f, 0.f, 0.f, 0.f);

    for (int k0 = 0; k0 < 256; k0 += 16) {
        {
            int r = tid >> 1, kq = (tid & 1) * 8;
            const float* src = d_h + (m0 + r) * H1 + k0 + kq;
            float4 v0 = *(const float4*)(src);
            float4 v1 = *(const float4*)(src + 4);
            float v[8] = {v0.x, v0.y, v0.z, v0.w, v1.x, v1.y, v1.z, v1.w};
            #pragma unroll
            for (int i = 0; i < 8; i++) tf32_split(v[i], Ah[kq + i][r], Al[kq + i][r]);
        }
        {
            int kr = tid >> 4, nq = (tid & 15) * 4;
            float4 bv = *(const float4*)(w + (k0 + kr) * H2 + n0 + nq);
            float v[4] = {bv.x, bv.y, bv.z, bv.w};
            #pragma unroll
            for (int i = 0; i < 4; i++) tf32_split(v[i], Bh[kr][nq + i], Bl[kr][nq + i]);
        }
        __syncthreads();
        #pragma unroll
        for (int ks = 0; ks < 16; ks += 8) {
            unsigned ah[2][4], al[2][4], bh[4][2], bl[4][2];
            int kr = ks + (lane & 3);
            int mr = warp_m * 32 + (lane >> 2);
            #pragma unroll
            for (int tm = 0; tm < 2; tm++) {
                int m = mr + tm * 16;
                ah[tm][0] = Ah[kr][m];     ah[tm][1] = Ah[kr][m + 8];
                ah[tm][2] = Ah[kr + 4][m]; ah[tm][3] = Ah[kr + 4][m + 8];
                al[tm][0] = Al[kr][m];     al[tm][1] = Al[kr][m + 8];
                al[tm][2] = Al[kr + 4][m]; al[tm][3] = Al[kr + 4][m + 8];
            }
            int nc = warp_n * 32 + (lane >> 2);
            #pragma unroll
            for (int tn = 0; tn < 4; tn++) {
                int nn = nc + tn * 8;
                bh[tn][0] = Bh[kr][nn]; bh[tn][1] = Bh[kr + 4][nn];
                bl[tn][0] = Bl[kr][nn]; bl[tn][1] = Bl[kr + 4][nn];
            }
            #pragma unroll
            for (int tm = 0; tm < 2; tm++)
                #pragma unroll
                for (int tn = 0; tn < 4; tn++) {
                    mma_tf32(dacc[tm][tn], ah[tm], bh[tn]);
                    mma_tf32(dacc[tm][tn], ah[tm], bl[tn]);
                    mma_tf32(dacc[tm][tn], al[tm], bh[tn]);
                }
        }
        __syncthreads();
    }
    #pragma unroll
    for (int tm = 0; tm < 2; tm++) {
        int rr = m0 + warp_m * 32 + tm * 16 + (lane >> 2);
        #pragma unroll
        for (int tn = 0; tn < 4; tn++) {
            int cc = n0 + warp_n * 32 + tn * 8 + (lane & 3) * 2;
            float4 d = dacc[tm][tn];
            *(float2*)(d_z + rr * H2 + cc)       = make_float2(d.x, d.y);
            *(float2*)(d_z + (rr + 8) * H2 + cc) = make_float2(d.z, d.w);
        }
    }
}

// ---------------- attention coefficients (+ fused pnorm in last block) ----------------
__global__ void k_attn_coef(const float* __restrict__ asrc, const float* __restrict__ adst,
                            const float* __restrict__ p, int n) {
    if (blockIdx.x == gridDim.x - 1) {
        __shared__ float sh[128];
        int t = threadIdx.x;
        if (t < 128) { float v = p[t]; sh[t] = v * v; }
        __syncthreads();
        for (int o = 64; o > 0; o >>= 1) {
            if (t < o) sh[t] += sh[t + o];
            __syncthreads();
        }
        if (t == 0) d_invpnorm = 1.0f / sqrtf(sh[0]);
        return;
    }
    int i    = (blockIdx.x * blockDim.x + threadIdx.x) >> 5;
    int lane = threadIdx.x & 31;
    if (i >= n) return;
    float4 zv = *(const float4*)(d_z + i * H2 + lane * 4);
    float4 av = *(const float4*)(asrc + lane * 4);
    float4 bv = *(const float4*)(adst + lane * 4);
    float s = zv.x * av.x + zv.y * av.y + zv.z * av.z + zv.w * av.w;
    float d = zv.x * bv.x + zv.y * bv.y + zv.z * bv.z + zv.w * bv.w;
    #pragma unroll
    for (int o = 16; o > 0; o >>= 1) {
        s += __shfl_down_sync(0xffffffffu, s, o);
        d += __shfl_down_sync(0xffffffffu, d, o);
    }
    if (lane == 0) { d_as[i] = s; d_ad[i] = d; }
}

// ---------------- fused GAT softmax-aggregate + relu + score ----------------
__global__ void k_gat(const float* __restrict__ gb, const float* __restrict__ p) {
    int node = (blockIdx.x * blockDim.x + threadIdx.x) >> 5;
    int lane = threadIdx.x & 31;
    if (node >= NTOT) return;
    int beg = d_cstart[node], cnt = d_cntin[node];
    float ad_c = d_ad[node];
    float eself = lrelu(d_as[node] + ad_c);
    // pass 1: segment max (exact, order-free)
    float m = eself;
    for (int j = lane; j < cnt; j += 32) {
        int r = __ldg(&d_csr[beg + j]);
        m = fmaxf(m, lrelu(__ldg(&d_as[r]) + ad_c));
    }
    #pragma unroll
    for (int o = 16; o > 0; o >>= 1) m = fmaxf(m, __shfl_xor_sync(0xffffffffu, m, o));
    // pass 2: ssum in edge order, self last
    float ssum = 0.f;
    for (int j = 0; j < cnt; j++) {
        int r = __ldg(&d_csr[beg + j]);
        ssum = __fadd_rn(ssum, expf(lrelu(__ldg(&d_as[r]) + ad_c) - m));
    }
    float pself = expf(eself - m);
    ssum = __fadd_rn(ssum, pself);
    // pass 3: aggregate alpha*z in edge order, self last
    float4 acc = make_float4(0.f, 0.f, 0.f, 0.f);
    int r = (cnt > 0) ? __ldg(&d_csr[beg]) : 0;
    for (int j = 0; j < cnt; j++) {
        int rn = (j + 1 < cnt) ? __ldg(&d_csr[beg + j + 1]) : 0;   // pipeline next index
        float alpha = expf(lrelu(__ldg(&d_as[r]) + ad_c) - m) / ssum;
        float4 zv = *(const float4*)(d_z + r * H2 + lane * 4);
        acc.x = __fadd_rn(acc.x, __fmul_rn(alpha, zv.x));
        acc.y = __fadd_rn(acc.y, __fmul_rn(alpha, zv.y));
        acc.z = __fadd_rn(acc.z, __fmul_rn(alpha, zv.z));
        acc.w = __fadd_rn(acc.w, __fmul_rn(alpha, zv.w));
        r = rn;
    }
    float aself = pself / ssum;
    float4 zc = *(const float4*)(d_z + node * H2 + lane * 4);
    float4 bv = *(const float4*)(gb + lane * 4);
    float4 g;
    g.x = fmaxf(__fadd_rn(acc.x, __fmul_rn(aself, zc.x)) + bv.x, 0.f);
    g.y = fmaxf(__fadd_rn(acc.y, __fmul_rn(aself, zc.y)) + bv.y, 0.f);
    g.z = fmaxf(__fadd_rn(acc.z, __fmul_rn(aself, zc.z)) + bv.z, 0.f);
    g.w = fmaxf(__fadd_rn(acc.w, __fmul_rn(aself, zc.w)) + bv.w, 0.f);
    *(float4*)(d_g + node * H2 + lane * 4) = g;
    float4 pv = *(const float4*)(p + lane * 4);
    float sc = g.x * pv.x + g.y * pv.y + g.z * pv.z + g.w * pv.w;
    #pragma unroll
    for (int o = 16; o > 0; o >>= 1) sc += __shfl_down_sync(0xffffffffu, sc, o);
    if (lane == 0) d_score[node] = tanhf(sc * d_invpnorm);
}

// ---------------- top-k pool (bitonic) + gated mean ----------------
__global__ __launch_bounds__(256) void k_topk_pool() {
    __shared__ float sv[NPG];
    __shared__ int   si[NPG];
    __shared__ float part[256];
    int b = blockIdx.x, t = threadIdx.x;
    int base = b * NPG;
    sv[t]       = d_score[base + t];       si[t]       = t;
    sv[t + 256] = d_score[base + t + 256]; si[t + 256] = t + 256;
    __syncthreads();
    for (int k = 2; k <= NPG; k <<= 1) {
        for (int j = k >> 1; j > 0; j >>= 1) {
            #pragma unroll
            for (int s = 0; s < 2; s++) {
                int i = t + s * 256;
                int ixj = i ^ j;
                if (ixj > i) {
                    bool up = ((i & k) == 0);
                    float vi = sv[i], vj = sv[ixj];
                    bool sw = up ? (vi < vj) : (vi > vj);
                    if (sw) {
                        sv[i] = vj; sv[ixj] = vi;
                        int ti = si[i]; si[i] = si[ixj]; si[ixj] = ti;
                    }
                }
            }
            __syncthreads();
        }
    }
    int d = t & 127, half = t >> 7;
    float acc = 0.f;
    for (int j = half * 128; j < half * 128 + 128; j++)
        acc += d_g[(base + si[j]) * H2 + d] * sv[j];
    part[t] = acc;
    __syncthreads();
    if (t < 128) d_gm[b * H2 + t] = (part[t] + part[t + 128]) * (1.0f / (float)KPOOL);
}

// ---------------- MLP head ----------------
__global__ __launch_bounds__(256) void k_mlp(const float* __restrict__ w1,
                                             const float* __restrict__ b1,
                                             const float* __restrict__ w2,
                                             const float* __restrict__ b2,
                                             float* __restrict__ out) {
    __shared__ float sgm[H2];
    __shared__ float red[256];
    int b = blockIdx.x, t = threadIdx.x;
    if (t < H2) sgm[t] = d_gm[b * H2 + t];
    __syncthreads();
    float acc = b1[t];
    #pragma unroll 8
    for (int k = 0; k < H2; k++) acc += sgm[k] * w1[k * H1 + t];
    red[t] = fmaxf(acc, 0.f) * w2[t];
    __syncthreads();
    for (int o = 128; o > 0; o >>= 1) {
        if (t < o) red[t] += red[t + o];
        __syncthreads();
    }
    if (t == 0) out[b] = red[0] + b2[0];
}

// ---------------- launch ----------------
extern "C" void kernel_launch(void* const* d_in, const int* in_sizes, int n_in,
                              void* d_out, int out_size) {
    const float* x     = (const float*)d_in[0];
    const int*   ei    = (const int*)  d_in[1];
    const float* cw0   = (const float*)d_in[3];
    const float* cw1   = (const float*)d_in[4];
    const float* cb    = (const float*)d_in[5];
    const float* gw    = (const float*)d_in[6];
    const float* gas   = (const float*)d_in[7];
    const float* gad   = (const float*)d_in[8];
    const float* gb    = (const float*)d_in[9];
    const float* pp    = (const float*)d_in[10];
    const float* l1w   = (const float*)d_in[11];
    const float* l1b   = (const float*)d_in[12];
    const float* l2w   = (const float*)d_in[13];
    const float* l2b   = (const float*)d_in[14];
    float* out = (float*)d_out;

    int n = in_sizes[0] / IND;          // 65536
    int E = in_sizes[1] / 2;            // 524288
    const int* row = ei;
    const int* col = ei + E;

    // single-kernel per-graph CSR build (sorted buckets -> reference order)
    k_build<<<NGRAPH, NPG>>>(row, col);

    // ChebConv
    k_cheb_gather<<<NTOT * 32 / 256, 256>>>(x);
    dim3 gh(H1 / 64, NTOT / 128);
    k_gemm_h_tc<<<gh, 256>>>(x, cw0, cw1, cb);

    // GAT
    dim3 gz(H2 / 64, NTOT / 128);
    k_gemm_z_tc<<<gz, 256>>>(gw);
    k_attn_coef<<<(n * 32 + 255) / 256 + 1, 256>>>(gas, gad, pp, n);
    k_gat<<<NTOT * 32 / 256, 256>>>(gb, pp);

    // Pool + head
    k_topk_pool<<<NGRAPH, 256>>>();
    k_mlp<<<NGRAPH, 256>>>(l1w, l1b, l2w, l2b, out);
}

// round 7
// speedup vs baseline: 1.9359x; 1.1103x over previous
#include <cuda_runtime.h>
#include <math.h>

#define NTOT   65536
#define NGRAPH 128
#define NPG    512
#define EPG    4096
#define KPOOL  256
#define EDG    524288
#define IND    128
#define H1     256
#define H2     128

// ---------------- scratch (device globals; no allocation) ----------------
__device__ float    d_dinv[NTOT];
__device__ int      d_cntin[NTOT];     // in-degree (col)
__device__ int      d_cstart[NTOT];    // CSR bucket starts (global edge offsets)
__device__ int      d_csr[EDG];        // source node ids, grouped by dst, edge-ascending
__device__ float    d_tx1[NTOT * IND];
__device__ float    d_h  [NTOT * H1];
__device__ float    d_z  [NTOT * H2];
__device__ float    d_as [NTOT];
__device__ float    d_ad [NTOT];
__device__ float    d_g  [NTOT * H2];
__device__ float    d_score[NTOT];
__device__ float    d_gm [NGRAPH * H2];
__device__ float    d_invpnorm;

// ---------------- helpers ----------------
__device__ __forceinline__ float lrelu(float x) { return x > 0.f ? x : 0.2f * x; }

__device__ __forceinline__ void tf32_split(float x, unsigned& hi, unsigned& lo) {
    unsigned h;
    asm("cvt.rna.tf32.f32 %0, %1;" : "=r"(h) : "f"(x));
    float hf = __uint_as_float(h);
    float lf = __fsub_rn(x, hf);
    unsigned l;
    asm("cvt.rna.tf32.f32 %0, %1;" : "=r"(l) : "f"(lf));
    hi = h; lo = l;
}

__device__ __forceinline__ void mma_tf32(float4& d, const unsigned* a, const unsigned* b) {
    asm volatile(
        "mma.sync.aligned.m16n8k8.row.col.f32.tf32.tf32.f32 "
        "{%0,%1,%2,%3}, {%4,%5,%6,%7}, {%8,%9}, {%0,%1,%2,%3};\n"
        : "+f"(d.x), "+f"(d.y), "+f"(d.z), "+f"(d.w)
        : "r"(a[0]), "r"(a[1]), "r"(a[2]), "r"(a[3]), "r"(b[0]), "r"(b[1]));
}

// ---------------- fused per-graph CSR build ----------------
__global__ __launch_bounds__(512) void k_build(const int* __restrict__ row,
                                               const int* __restrict__ col) {
    __shared__ int sedge[EPG];     // (col_local<<16) | row_local
    __shared__ int sbuck[EPG];     // (e_local<<9) | row_local, per-bucket
    __shared__ int scnt[NPG];
    __shared__ int sdeg[NPG];
    __shared__ int sexcl[NPG];
    __shared__ int sfill[NPG];
    int b = blockIdx.x, t = threadIdx.x;
    int ebase = b * EPG, nbase = b * NPG;

    scnt[t] = 0; sdeg[t] = 0; sfill[t] = 0;
    __syncthreads();

    #pragma unroll
    for (int i = 0; i < EPG / NPG; i++) {
        int e = t + i * NPG;
        int rl = row[ebase + e] - nbase;
        int cl = col[ebase + e] - nbase;
        sedge[e] = (cl << 16) | rl;
        atomicAdd(&scnt[cl], 1);
        atomicAdd(&sdeg[rl], 1);
    }
    __syncthreads();

    int v = scnt[t];
    sexcl[t] = v;
    __syncthreads();
    for (int o = 1; o < NPG; o <<= 1) {
        int tmp = (t >= o) ? sexcl[t - o] : 0;
        __syncthreads();
        sexcl[t] += tmp;
        __syncthreads();
    }
    int excl = sexcl[t] - v;
    __syncthreads();
    sexcl[t] = excl;

    d_cstart[nbase + t] = ebase + excl;
    d_cntin[nbase + t]  = v;
    float dg = (float)sdeg[t];
    d_dinv[nbase + t] = dg > 0.f ? rsqrtf(fmaxf(dg, 1.0f)) : 0.f;
    __syncthreads();

    #pragma unroll
    for (int i = 0; i < EPG / NPG; i++) {
        int e = t + i * NPG;
        int pv = sedge[e];
        int cl = pv >> 16;
        int pos = atomicAdd(&sfill[cl], 1);
        sbuck[sexcl[cl] + pos] = (e << 9) | (pv & 511);
    }
    __syncthreads();

    int beg = sexcl[t], cnt = scnt[t];
    for (int i = beg + 1; i < beg + cnt; i++) {
        int key = sbuck[i];
        int j = i - 1;
        while (j >= beg && sbuck[j] > key) { sbuck[j + 1] = sbuck[j]; j--; }
        sbuck[j + 1] = key;
    }
    for (int j = 0; j < cnt; j++)
        d_csr[ebase + beg + j] = nbase + (sbuck[beg + j] & 511);
}

// ---------------- ChebConv gather (reference edge order, no FMA contraction) ----------------
__global__ void k_cheb_gather(const float* __restrict__ x) {
    int node = (blockIdx.x * blockDim.x + threadIdx.x) >> 5;
    int lane = threadIdx.x & 31;
    if (node >= NTOT) return;
    int beg = d_cstart[node], cnt = d_cntin[node];
    float dc = d_dinv[node];
    float4 acc = make_float4(0.f, 0.f, 0.f, 0.f);
    int r = (cnt > 0) ? __ldg(&d_csr[beg]) : 0;
    for (int j = 0; j < cnt; j++) {
        int rn = (j + 1 < cnt) ? __ldg(&d_csr[beg + j + 1]) : 0;
        float w = -(__ldg(&d_dinv[r]) * dc);
        float4 xv = *(const float4*)(x + r * IND + lane * 4);
        acc.x = __fadd_rn(acc.x, __fmul_rn(w, xv.x));
        acc.y = __fadd_rn(acc.y, __fmul_rn(w, xv.y));
        acc.z = __fadd_rn(acc.z, __fmul_rn(w, xv.z));
        acc.w = __fadd_rn(acc.w, __fmul_rn(w, xv.w));
        r = rn;
    }
    *(float4*)(d_tx1 + node * IND + lane * 4) = acc;
}

// ---------------- tensor-core GEMMs : raw-fp32 smem, split-in-registers ----------------
// h = relu(x@W0 + tx1@W1 + b) : K = 128(x) + 128(tx1), N=256
__global__ __launch_bounds__(256) void k_gemm_h_tc(const float* __restrict__ x,
                                                   const float* __restrict__ w0,
                                                   const float* __restrict__ w1,
                                                   const float* __restrict__ bias) {
    __shared__ float As[16][136];
    __shared__ float Bs[16][72];
    int tid = threadIdx.x;
    int lane = tid & 31, wid = tid >> 5;
    int warp_m = wid & 3, warp_n = wid >> 2;
    int m0 = blockIdx.y * 128, n0 = blockIdx.x * 64;
    float4 dacc[2][4];
    #pragma unroll
    for (int i = 0; i < 2; i++)
        #pragma unroll
        for (int j = 0; j < 4; j++) dacc[i][j] = make_float4(0.f, 0.f, 0.f, 0.f);

    for (int k0 = 0; k0 < 256; k0 += 16) {
        {   // A tile raw: 128 rows x 16 k ; thread loads 8 consecutive k of one row
            int r = tid >> 1, kq = (tid & 1) * 8;
            const float* base = (k0 < 128) ? (x + k0) : (d_tx1 + (k0 - 128));
            const float* src = base + (m0 + r) * IND + kq;
            float4 v0 = *(const float4*)(src);
            float4 v1 = *(const float4*)(src + 4);
            As[kq + 0][r] = v0.x; As[kq + 1][r] = v0.y;
            As[kq + 2][r] = v0.z; As[kq + 3][r] = v0.w;
            As[kq + 4][r] = v1.x; As[kq + 5][r] = v1.y;
            As[kq + 6][r] = v1.z; As[kq + 7][r] = v1.w;
        }
        {   // B tile raw: 16 k x 64 n
            int kr = tid >> 4, nq = (tid & 15) * 4;
            int kk = k0 + kr;
            const float* src = (kk < 128) ? (w0 + kk * H1 + n0 + nq)
                                          : (w1 + (kk - 128) * H1 + n0 + nq);
            float4 bv = *(const float4*)src;
            Bs[kr][nq + 0] = bv.x; Bs[kr][nq + 1] = bv.y;
            Bs[kr][nq + 2] = bv.z; Bs[kr][nq + 3] = bv.w;
        }
        __syncthreads();
        #pragma unroll
        for (int ks = 0; ks < 16; ks += 8) {
            int kr = ks + (lane & 3);
            // B fragments for all tn (split in regs)
            unsigned bh[4][2], bl[4][2];
            int nc = warp_n * 32 + (lane >> 2);
            #pragma unroll
            for (int tn = 0; tn < 4; tn++) {
                int nn = nc + tn * 8;
                tf32_split(Bs[kr][nn],     bh[tn][0], bl[tn][0]);
                tf32_split(Bs[kr + 4][nn], bh[tn][1], bl[tn][1]);
            }
            int mr = warp_m * 32 + (lane >> 2);
            #pragma unroll
            for (int tm = 0; tm < 2; tm++) {
                int m = mr + tm * 16;
                unsigned ah[4], al[4];
                tf32_split(As[kr][m],         ah[0], al[0]);
                tf32_split(As[kr][m + 8],     ah[1], al[1]);
                tf32_split(As[kr + 4][m],     ah[2], al[2]);
                tf32_split(As[kr + 4][m + 8], ah[3], al[3]);
                #pragma unroll
                for (int tn = 0; tn < 4; tn++) {
                    mma_tf32(dacc[tm][tn], ah, bh[tn]);
                    mma_tf32(dacc[tm][tn], ah, bl[tn]);
                    mma_tf32(dacc[tm][tn], al, bh[tn]);
                }
            }
        }
        __syncthreads();
    }
    #pragma unroll
    for (int tm = 0; tm < 2; tm++) {
        int rr = m0 + warp_m * 32 + tm * 16 + (lane >> 2);
        #pragma unroll
        for (int tn = 0; tn < 4; tn++) {
            int cc = n0 + warp_n * 32 + tn * 8 + (lane & 3) * 2;
            float bx = bias[cc], by = bias[cc + 1];
            float4 d = dacc[tm][tn];
            *(float2*)(d_h + rr * H1 + cc) =
                make_float2(fmaxf(d.x + bx, 0.f), fmaxf(d.y + by, 0.f));
            *(float2*)(d_h + (rr + 8) * H1 + cc) =
                make_float2(fmaxf(d.z + bx, 0.f), fmaxf(d.w + by, 0.f));
        }
    }
}

// z = h @ gat_w : K=256, N=128
__global__ __launch_bounds__(256) void k_gemm_z_tc(const float* __restrict__ w) {
    __shared__ float As[16][136];
    __shared__ float Bs[16][72];
    int tid = threadIdx.x;
    int lane = tid & 31, wid = tid >> 5;
    int warp_m = wid & 3, warp_n = wid >> 2;
    int m0 = blockIdx.y * 128, n0 = blockIdx.x * 64;
    float4 dacc[2][4];
    #pragma unroll
    for (int i = 0; i < 2; i++)
        #pragma unroll
        for (int j = 0; j < 4; j++) dacc[i][j] = make_float4(0.f, 0.f, 0.f, 0.f);

    for (int k0 = 0; k0 < 256; k0 += 16) {
        {
            int r = tid >> 1, kq = (tid & 1) * 8;
            const float* src = d_h + (m0 + r) * H1 + k0 + kq;
            float4 v0 = *(const float4*)(src);
            float4 v1 = *(const float4*)(src + 4);
            As[kq + 0][r] = v0.x; As[kq + 1][r] = v0.y;
            As[kq + 2][r] = v0.z; As[kq + 3][r] = v0.w;
            As[kq + 4][r] = v1.x; As[kq + 5][r] = v1.y;
            As[kq + 6][r] = v1.z; As[kq + 7][r] = v1.w;
        }
        {
            int kr = tid >> 4, nq = (tid & 15) * 4;
            float4 bv = *(const float4*)(w + (k0 + kr) * H2 + n0 + nq);
            Bs[kr][nq + 0] = bv.x; Bs[kr][nq + 1] = bv.y;
            Bs[kr][nq + 2] = bv.z; Bs[kr][nq + 3] = bv.w;
        }
        __syncthreads();
        #pragma unroll
        for (int ks = 0; ks < 16; ks += 8) {
            int kr = ks + (lane & 3);
            unsigned bh[4][2], bl[4][2];
            int nc = warp_n * 32 + (lane >> 2);
            #pragma unroll
            for (int tn = 0; tn < 4; tn++) {
                int nn = nc + tn * 8;
                tf32_split(Bs[kr][nn],     bh[tn][0], bl[tn][0]);
                tf32_split(Bs[kr + 4][nn], bh[tn][1], bl[tn][1]);
            }
            int mr = warp_m * 32 + (lane >> 2);
            #pragma unroll
            for (int tm = 0; tm < 2; tm++) {
                int m = mr + tm * 16;
                unsigned ah[4], al[4];
                tf32_split(As[kr][m],         ah[0], al[0]);
                tf32_split(As[kr][m + 8],     ah[1], al[1]);
                tf32_split(As[kr + 4][m],     ah[2], al[2]);
                tf32_split(As[kr + 4][m + 8], ah[3], al[3]);
                #pragma unroll
                for (int tn = 0; tn < 4; tn++) {
                    mma_tf32(dacc[tm][tn], ah, bh[tn]);
                    mma_tf32(dacc[tm][tn], ah, bl[tn]);
                    mma_tf32(dacc[tm][tn], al, bh[tn]);
                }
            }
        }
        __syncthreads();
    }
    #pragma unroll
    for (int tm = 0; tm < 2; tm++) {
        int rr = m0 + warp_m * 32 + tm * 16 + (lane >> 2);
        #pragma unroll
        for (int tn = 0; tn < 4; tn++) {
            int cc = n0 + warp_n * 32 + tn * 8 + (lane & 3) * 2;
            float4 d = dacc[tm][tn];
            *(float2*)(d_z + rr * H2 + cc)       = make_float2(d.x, d.y);
            *(float2*)(d_z + (rr + 8) * H2 + cc) = make_float2(d.z, d.w);
        }
    }
}

// ---------------- attention coefficients (+ fused pnorm in last block) ----------------
__global__ void k_attn_coef(const float* __restrict__ asrc, const float* __restrict__ adst,
                            const float* __restrict__ p, int n) {
    if (blockIdx.x == gridDim.x - 1) {
        __shared__ float sh[128];
        int t = threadIdx.x;
        if (t < 128) { float v = p[t]; sh[t] = v * v; }
        __syncthreads();
        for (int o = 64; o > 0; o >>= 1) {
            if (t < o) sh[t] += sh[t + o];
            __syncthreads();
        }
        if (t == 0) d_invpnorm = 1.0f / sqrtf(sh[0]);
        return;
    }
    int i    = (blockIdx.x * blockDim.x + threadIdx.x) >> 5;
    int lane = threadIdx.x & 31;
    if (i >= n) return;
    float4 zv = *(const float4*)(d_z + i * H2 + lane * 4);
    float4 av = *(const float4*)(asrc + lane * 4);
    float4 bv = *(const float4*)(adst + lane * 4);
    float s = zv.x * av.x + zv.y * av.y + zv.z * av.z + zv.w * av.w;
    float d = zv.x * bv.x + zv.y * bv.y + zv.z * bv.z + zv.w * bv.w;
    #pragma unroll
    for (int o = 16; o > 0; o >>= 1) {
        s += __shfl_down_sync(0xffffffffu, s, o);
        d += __shfl_down_sync(0xffffffffu, d, o);
    }
    if (lane == 0) { d_as[i] = s; d_ad[i] = d; }
}

// ---------------- fused GAT softmax-aggregate + relu + score ----------------
__global__ void k_gat(const float* __restrict__ gb, const float* __restrict__ p) {
    int node = (blockIdx.x * blockDim.x + threadIdx.x) >> 5;
    int lane = threadIdx.x & 31;
    if (node >= NTOT) return;
    int beg = d_cstart[node], cnt = d_cntin[node];
    float ad_c = d_ad[node];
    float eself = lrelu(d_as[node] + ad_c);
    float m = eself;
    for (int j = lane; j < cnt; j += 32) {
        int r = __ldg(&d_csr[beg + j]);
        m = fmaxf(m, lrelu(__ldg(&d_as[r]) + ad_c));
    }
    #pragma unroll
    for (int o = 16; o > 0; o >>= 1) m = fmaxf(m, __shfl_xor_sync(0xffffffffu, m, o));
    float ssum = 0.f;
    for (int j = 0; j < cnt; j++) {
        int r = __ldg(&d_csr[beg + j]);
        ssum = __fadd_rn(ssum, expf(lrelu(__ldg(&d_as[r]) + ad_c) - m));
    }
    float pself = expf(eself - m);
    ssum = __fadd_rn(ssum, pself);
    float4 acc = make_float4(0.f, 0.f, 0.f, 0.f);
    int r = (cnt > 0) ? __ldg(&d_csr[beg]) : 0;
    for (int j = 0; j < cnt; j++) {
        int rn = (j + 1 < cnt) ? __ldg(&d_csr[beg + j + 1]) : 0;
        float alpha = expf(lrelu(__ldg(&d_as[r]) + ad_c) - m) / ssum;
        float4 zv = *(const float4*)(d_z + r * H2 + lane * 4);
        acc.x = __fadd_rn(acc.x, __fmul_rn(alpha, zv.x));
        acc.y = __fadd_rn(acc.y, __fmul_rn(alpha, zv.y));
        acc.z = __fadd_rn(acc.z, __fmul_rn(alpha, zv.z));
        acc.w = __fadd_rn(acc.w, __fmul_rn(alpha, zv.w));
        r = rn;
    }
    float aself = pself / ssum;
    float4 zc = *(const float4*)(d_z + node * H2 + lane * 4);
    float4 bv = *(const float4*)(gb + lane * 4);
    float4 g;
    g.x = fmaxf(__fadd_rn(acc.x, __fmul_rn(aself, zc.x)) + bv.x, 0.f);
    g.y = fmaxf(__fadd_rn(acc.y, __fmul_rn(aself, zc.y)) + bv.y, 0.f);
    g.z = fmaxf(__fadd_rn(acc.z, __fmul_rn(aself, zc.z)) + bv.z, 0.f);
    g.w = fmaxf(__fadd_rn(acc.w, __fmul_rn(aself, zc.w)) + bv.w, 0.f);
    *(float4*)(d_g + node * H2 + lane * 4) = g;
    float4 pv = *(const float4*)(p + lane * 4);
    float sc = g.x * pv.x + g.y * pv.y + g.z * pv.z + g.w * pv.w;
    #pragma unroll
    for (int o = 16; o > 0; o >>= 1) sc += __shfl_down_sync(0xffffffffu, sc, o);
    if (lane == 0) d_score[node] = tanhf(sc * d_invpnorm);
}

// ---------------- top-k pool (bitonic) + gated mean ----------------
__global__ __launch_bounds__(256) void k_topk_pool() {
    __shared__ float sv[NPG];
    __shared__ int   si[NPG];
    __shared__ float part[256];
    int b = blockIdx.x, t = threadIdx.x;
    int base = b * NPG;
    sv[t]       = d_score[base + t];       si[t]       = t;
    sv[t + 256] = d_score[base + t + 256]; si[t + 256] = t + 256;
    __syncthreads();
    for (int k = 2; k <= NPG; k <<= 1) {
        for (int j = k >> 1; j > 0; j >>= 1) {
            #pragma unroll
            for (int s = 0; s < 2; s++) {
                int i = t + s * 256;
                int ixj = i ^ j;
                if (ixj > i) {
                    bool up = ((i & k) == 0);
                    float vi = sv[i], vj = sv[ixj];
                    bool sw = up ? (vi < vj) : (vi > vj);
                    if (sw) {
                        sv[i] = vj; sv[ixj] = vi;
                        int ti = si[i]; si[i] = si[ixj]; si[ixj] = ti;
                    }
                }
            }
            __syncthreads();
        }
    }
    int d = t & 127, half = t >> 7;
    float acc = 0.f;
    for (int j = half * 128; j < half * 128 + 128; j++)
        acc += d_g[(base + si[j]) * H2 + d] * sv[j];
    part[t] = acc;
    __syncthreads();
    if (t < 128) d_gm[b * H2 + t] = (part[t] + part[t + 128]) * (1.0f / (float)KPOOL);
}

// ---------------- MLP head ----------------
__global__ __launch_bounds__(256) void k_mlp(const float* __restrict__ w1,
                                             const float* __restrict__ b1,
                                             const float* __restrict__ w2,
                                             const float* __restrict__ b2,
                                             float* __restrict__ out) {
    __shared__ float sgm[H2];
    __shared__ float red[256];
    int b = blockIdx.x, t = threadIdx.x;
    if (t < H2) sgm[t] = d_gm[b * H2 + t];
    __syncthreads();
    float acc = b1[t];
    #pragma unroll 8
    for (int k = 0; k < H2; k++) acc += sgm[k] * w1[k * H1 + t];
    red[t] = fmaxf(acc, 0.f) * w2[t];
    __syncthreads();
    for (int o = 128; o > 0; o >>= 1) {
        if (t < o) red[t] += red[t + o];
        __syncthreads();
    }
    if (t == 0) out[b] = red[0] + b2[0];
}

// ---------------- launch ----------------
extern "C" void kernel_launch(void* const* d_in, const int* in_sizes, int n_in,
                              void* d_out, int out_size) {
    const float* x     = (const float*)d_in[0];
    const int*   ei    = (const int*)  d_in[1];
    const float* cw0   = (const float*)d_in[3];
    const float* cw1   = (const float*)d_in[4];
    const float* cb    = (const float*)d_in[5];
    const float* gw    = (const float*)d_in[6];
    const float* gas   = (const float*)d_in[7];
    const float* gad   = (const float*)d_in[8];
    const float* gb    = (const float*)d_in[9];
    const float* pp    = (const float*)d_in[10];
    const float* l1w   = (const float*)d_in[11];
    const float* l1b   = (const float*)d_in[12];
    const float* l2w   = (const float*)d_in[13];
    const float* l2b   = (const float*)d_in[14];
    float* out = (float*)d_out;

    int n = in_sizes[0] / IND;          // 65536
    int E = in_sizes[1] / 2;            // 524288
    const int* row = ei;
    const int* col = ei + E;

    // single-kernel per-graph CSR build (sorted buckets -> reference order)
    k_build<<<NGRAPH, NPG>>>(row, col);

    // ChebConv
    k_cheb_gather<<<NTOT * 32 / 256, 256>>>(x);
    dim3 gh(H1 / 64, NTOT / 128);
    k_gemm_h_tc<<<gh, 256>>>(x, cw0, cw1, cb);

    // GAT
    dim3 gz(H2 / 64, NTOT / 128);
    k_gemm_z_tc<<<gz, 256>>>(gw);
    k_attn_coef<<<(n * 32 + 255) / 256 + 1, 256>>>(gas, gad, pp, n);
    k_gat<<<NTOT * 32 / 256, 256>>>(gb, pp);

    // Pool + head
    k_topk_pool<<<NGRAPH, 256>>>();
    k_mlp<<<NGRAPH, 256>>>(l1w, l1b, l2w, l2b, out);
}